// round 5
// baseline (speedup 1.0000x reference)
#include <cuda_runtime.h>
#include <cuda_bf16.h>
#include <math.h>

// Problem constants
#define PH     5
#define NCOIL  16          // ch*d = 8*2
#define NIM    320         // H = W
#define KOS    640         // 2x oversampled grid
#define KLEN   16000
#define JTAPS  6
#define ALPHA_F 14.04f     // 2.34 * 6
#define PI_F   3.14159265358979323846f

// ---------------------------------------------------------------------------
// Static device scratch (no allocations allowed)
//   g_R: stage-1 out, layout [p][q][c][n]   (p<5, q<640, c<16, n<320)
//   g_G: stage-2 out, layout [p][k][q][c]   (coil innermost for interp)
// ---------------------------------------------------------------------------
__device__ float2 g_R[PH * KOS * NCOIL * NIM];      // 131 MB
__device__ float2 g_G[PH * KOS * KOS * NCOIL];      // 262 MB
__device__ float2 g_tw[KOS];                        // W640^t table
__device__ float  g_sh[NIM];                        // apodization (sh == sw)
__device__ float  g_inv_i0a;                        // 1 / I0(alpha)

// ---------------------------------------------------------------------------
// Compile-time twiddle tables (fold to FFMA immediates after unroll)
// ---------------------------------------------------------------------------
// W5^t = e^{-2 pi i t / 5}
__device__ constexpr float W5R[5] = {
    1.0f, 0.30901699437495f, -0.80901699437495f, -0.80901699437495f, 0.30901699437495f };
__device__ constexpr float W5I[5] = {
    0.0f, -0.95105651629515f, -0.58778525229247f, 0.58778525229247f, 0.95105651629515f };
// W20^t = e^{-2 pi i t / 20}
__device__ constexpr float W20R[20] = {
    1.0f, 0.95105651629515f, 0.80901699437495f, 0.58778525229247f, 0.30901699437495f,
    0.0f, -0.30901699437495f, -0.58778525229247f, -0.80901699437495f, -0.95105651629515f,
    -1.0f, -0.95105651629515f, -0.80901699437495f, -0.58778525229247f, -0.30901699437495f,
    0.0f, 0.30901699437495f, 0.58778525229247f, 0.80901699437495f, 0.95105651629515f };
__device__ constexpr float W20I[20] = {
    0.0f, -0.30901699437495f, -0.58778525229247f, -0.80901699437495f, -0.95105651629515f,
    -1.0f, -0.95105651629515f, -0.80901699437495f, -0.58778525229247f, -0.30901699437495f,
    0.0f, 0.30901699437495f, 0.58778525229247f, 0.80901699437495f, 0.95105651629515f,
    1.0f, 0.95105651629515f, 0.80901699437495f, 0.58778525229247f, 0.30901699437495f };
// W32^t = e^{-2 pi i t / 32}, t < 16
__device__ constexpr float W32R[16] = {
    1.0f, 0.98078528040323f, 0.92387953251129f, 0.83146961230255f,
    0.70710678118655f, 0.55557023301960f, 0.38268343236509f, 0.19509032201613f,
    0.0f, -0.19509032201613f, -0.38268343236509f, -0.55557023301960f,
    -0.70710678118655f, -0.83146961230255f, -0.92387953251129f, -0.98078528040323f };
__device__ constexpr float W32I[16] = {
    0.0f, -0.19509032201613f, -0.38268343236509f, -0.55557023301960f,
    -0.70710678118655f, -0.83146961230255f, -0.92387953251129f, -0.98078528040323f,
    -1.0f, -0.98078528040323f, -0.92387953251129f, -0.83146961230255f,
    -0.70710678118655f, -0.55557023301960f, -0.38268343236509f, -0.19509032201613f };
// 5-bit bit reversal
__device__ constexpr int BR5[32] = {
    0,16,8,24,4,20,12,28,2,18,10,26,6,22,14,30,
    1,17,9,25,5,21,13,29,3,19,11,27,7,23,15,31 };

// ---------------------------------------------------------------------------
// Modified Bessel I0 (Abramowitz & Stegun 9.8.1 / 9.8.2, rel err ~2e-7)
// ---------------------------------------------------------------------------
__device__ __forceinline__ float i0f_dev(float x) {
    if (x < 3.75f) {
        float t = x * (1.0f / 3.75f);
        t *= t;
        return 1.0f + t * (3.5156229f + t * (3.0899424f + t * (1.2067492f +
               t * (0.2659732f + t * (0.0360768f + t * 0.0045813f)))));
    } else {
        float t = 3.75f / x;
        float p = 0.39894228f + t * (0.01328592f + t * (0.00225319f +
                  t * (-0.00157565f + t * (0.00916281f + t * (-0.02057706f +
                  t * (0.02635537f + t * (-0.01647633f + t * 0.00392377f)))))));
        return p * expf(x) * rsqrtf(x);
    }
}

__global__ void init_tables_kernel() {
    int n = blockIdx.x * blockDim.x + threadIdx.x;   // 0..639
    if (n < NIM) {
        float i0a = i0f_dev(ALPHA_F);
        if (n == 0) g_inv_i0a = 1.0f / i0a;
        float nn = (float)(n - NIM / 2);
        float u  = nn * (1.0f / (float)KOS);
        float w  = PI_F * (float)JTAPS * u;
        float z2 = w * w - ALPHA_F * ALPHA_F;
        float z  = fmaxf(sqrtf(fabsf(z2)), 1e-6f);
        float core = (z2 > 0.0f) ? (sinf(z) / z) : (sinhf(z) / z);
        float ft = core * ((float)JTAPS / i0a);
        g_sh[n] = 1.0f / ft;
    }
    if (n < KOS) {
        float s, c;
        sincospif(-(float)n * (1.0f / 320.0f), &s, &c);
        g_tw[n] = make_float2(c, s);
    }
}

// ---------------------------------------------------------------------------
// Four-step 640-pt DFT of a zero-padded length-320 signal. Block = 256
// threads = 8 columns.
//   n = 32*n1 + n2 (n1<20, n2<32; nonzero n1<10),  k = k1 + 20*k2.
// Phase A (warp = column, lane = n2): 20-pt FFT over n1 as 4 x 5-pt DFTs +
//   W20 recombine (all constant twiddles), times W640^{n2 k1}; -> smem.
// Phase B (one thread per (column,k1), 160 threads): full 32-pt radix-2 DIT
//   FFT in registers with constant twiddles; -> smem reordered.
// Phase D: coalesced global store.
// MODE 1: stage-1 (apodized, image -> R[p][q][c][n])
// MODE 2: stage-2 (R -> G[p][k][q][c])
// ---------------------------------------------------------------------------
#define SQ_PAD 9           // Sq row stride (8 cols + 1 pad)
#define S_PAD 33           // S row stride (32 lanes + 1 pad)
#define BUF_F2 (KOS * SQ_PAD)   // 5760 float2 (>= 160*33 = 5280)

template <int MODE>
__global__ __launch_bounds__(256, 2) void fft640_kernel(
    const float2* __restrict__ in, float2* __restrict__ out)
{
    extern __shared__ float2 smem[];
    float2* tw  = smem;            // [640]
    float2* buf = smem + KOS;      // [BUF_F2]

    const int tid  = threadIdx.x;
    const int w    = tid >> 5;
    const int lane = tid & 31;

    for (int t = tid; t < KOS; t += 256) tw[t] = g_tw[t];
    __syncthreads();

    const int base_col = blockIdx.x * 8;
    const int col = base_col + w;

    // ================= Phase A =================
    {
        float xr[10], xi[10];
        const float2* ip = in + (size_t)col * NIM + lane;
        float shr = 1.0f;
        if (MODE == 1) shr = g_sh[col % NIM];
#pragma unroll
        for (int n1 = 0; n1 < 10; n1++) {
            float2 v = ip[n1 * 32];
            if (MODE == 1) {
                float s = shr * g_sh[n1 * 32 + lane];
                v.x *= s; v.y *= s;
            }
            xr[n1] = v.x; xi[n1] = v.y;
        }

        // four 5-pt DFTs over m of x[4m+r]  (only n1<10 nonzero)
        float f0r[5], f0i[5], f1r[5], f1i[5], f2r[5], f2i[5], f3r[5], f3i[5];
#pragma unroll
        for (int j = 0; j < 5; j++) {
            const int j2 = (2 * j) % 5;
            f0r[j] = xr[0] + (xr[4]*W5R[j] - xi[4]*W5I[j]) + (xr[8]*W5R[j2] - xi[8]*W5I[j2]);
            f0i[j] = xi[0] + (xr[4]*W5I[j] + xi[4]*W5R[j]) + (xr[8]*W5I[j2] + xi[8]*W5R[j2]);
            f1r[j] = xr[1] + (xr[5]*W5R[j] - xi[5]*W5I[j]) + (xr[9]*W5R[j2] - xi[9]*W5I[j2]);
            f1i[j] = xi[1] + (xr[5]*W5I[j] + xi[5]*W5R[j]) + (xr[9]*W5I[j2] + xi[9]*W5R[j2]);
            f2r[j] = xr[2] + (xr[6]*W5R[j] - xi[6]*W5I[j]);
            f2i[j] = xi[2] + (xr[6]*W5I[j] + xi[6]*W5R[j]);
            f3r[j] = xr[3] + (xr[7]*W5R[j] - xi[7]*W5I[j]);
            f3i[j] = xi[3] + (xr[7]*W5I[j] + xi[7]*W5R[j]);
        }
        // recombine to 20-pt, twiddle by W640^{n2 k1}, stash in smem
#pragma unroll
        for (int k = 0; k < 20; k++) {
            const int j = k % 5, ka = (2 * k) % 20, kb = (3 * k) % 20;
            float Xr = f0r[j]
                + (f1r[j]*W20R[k]  - f1i[j]*W20I[k])
                + (f2r[j]*W20R[ka] - f2i[j]*W20I[ka])
                + (f3r[j]*W20R[kb] - f3i[j]*W20I[kb]);
            float Xi = f0i[j]
                + (f1r[j]*W20I[k]  + f1i[j]*W20R[k])
                + (f2r[j]*W20I[ka] + f2i[j]*W20R[ka])
                + (f3r[j]*W20I[kb] + f3i[j]*W20R[kb]);
            float2 t6 = tw[lane * k];                // W640^{n2 k}
            float2 S;
            S.x = Xr * t6.x - Xi * t6.y;
            S.y = Xr * t6.y + Xi * t6.x;
            buf[(w * 20 + k) * S_PAD + lane] = S;
        }
    }
    __syncthreads();

    // ================= Phase B: per-thread 32-pt FFT =================
    float yr[32], yi[32];
    const bool active = (tid < 160);                 // (col_l, k1) = tid
    if (active) {
        const float2* Sp = buf + tid * S_PAD;
#pragma unroll
        for (int j = 0; j < 32; j++) {               // bit-reversed input
            float2 v = Sp[BR5[j]];
            yr[j] = v.x; yi[j] = v.y;
        }
#pragma unroll
        for (int s = 1; s <= 5; s++) {
            const int len = 1 << s, half = len >> 1, tsh = 5 - s;
#pragma unroll
            for (int g = 0; g < 32; g += len) {
#pragma unroll
                for (int j = 0; j < half; j++) {
                    const int ti = j << tsh;
                    const float twr = W32R[ti], twi = W32I[ti];
                    const int a = g + j, b = g + j + half;
                    float br = yr[b] * twr - yi[b] * twi;
                    float bi = yr[b] * twi + yi[b] * twr;
                    yr[b] = yr[a] - br; yi[b] = yi[a] - bi;
                    yr[a] = yr[a] + br; yi[a] = yi[a] + bi;
                }
            }
        }
    }
    __syncthreads();     // all phase-B smem reads complete before reuse

    if (active) {
        const int col_l = tid / 20;
        const int k1 = tid - col_l * 20;
#pragma unroll
        for (int k2 = 0; k2 < 32; k2++) {
            const int q = k1 + 20 * k2;
            buf[q * SQ_PAD + col_l] = make_float2(yr[k2], yi[k2]);
        }
    }
    __syncthreads();

    // ================= Phase D: coalesced global store =================
    size_t out_base; int stride_q;
    if (MODE == 1) {
        // col = (p*16+cc)*320 + n  ->  out[((p*640+q)*16+cc)*320 + n]
        int pc = base_col / NIM, n0 = base_col % NIM;
        int p = pc >> 4, cc = pc & 15;
        out_base = (size_t)p * (640u * 16u * 320u) + (size_t)cc * 320u + (size_t)n0;
        stride_q = 16 * 320;
    } else {
        // col = (p*640+qq)*16 + coil  ->  out[((p*640+k)*640+qq)*16 + coil]
        int pq = base_col >> 4, c0 = base_col & 15;
        int p = pq / KOS, qq = pq - p * KOS;
        out_base = (size_t)p * (640u * 640u * 16u) + (size_t)qq * 16u + (size_t)c0;
        stride_q = 640 * 16;
    }
#pragma unroll
    for (int i = 0; i < 20; i++) {
        int idx = i * 256 + tid;           // 0..5119
        int q = idx >> 3, c = idx & 7;
        out[out_base + (size_t)q * stride_q + c] = buf[q * SQ_PAD + c];
    }
}

// ---------------------------------------------------------------------------
// KB interpolation: 6x6 taps, 16 coils per point; G is coil-innermost so the
// 16 coil-lanes read 128B contiguous per tap.
// ---------------------------------------------------------------------------
__global__ __launch_bounds__(256) void interp_kernel(
    const float* __restrict__ traj, float2* __restrict__ out)
{
    __shared__ float s_wh[16][JTAPS], s_ww[16][JTAPS];
    __shared__ int   s_ih[16][JTAPS], s_iw[16][JTAPS];
    __shared__ float s_pr[16], s_pi[16];

    const int tid = threadIdx.x;
    const int cd  = tid & 15;                     // coil
    const int li  = tid >> 4;                     // point within block
    const int p   = blockIdx.y;
    const int l   = blockIdx.x * 16 + li;

    const float inv_i0a = g_inv_i0a;

    if (cd < 2) {
        float om = traj[(long)(p * 2 + cd) * KLEN + l];
        float t  = om * (320.0f / PI_F);
        float base = floorf(t - 3.0f);
#pragma unroll
        for (int j = 0; j < JTAPS; j++) {
            float kf  = base + (float)(j + 1);
            float u   = t - kf;
            float ua  = u * (1.0f / 3.0f);
            float arg = fmaxf(1.0f - ua * ua, 0.0f);
            float w   = i0f_dev(ALPHA_F * sqrtf(arg)) * inv_i0a;
            int ki  = (int)kf;
            int idx = ki % KOS; if (idx < 0) idx += KOS;
            if (cd == 0) { s_wh[li][j] = w; s_ih[li][j] = idx; }
            else         { s_ww[li][j] = w; s_iw[li][j] = idx; }
        }
        if (cd == 0) {
            float om1 = traj[(long)(p * 2 + 1) * KLEN + l];
            float th  = 160.0f * (om + om1);
            float sp, cp;
            sincosf(th, &sp, &cp);
            s_pr[li] = cp; s_pi[li] = sp;
        }
    }
    __syncthreads();

    const float2* Gp = g_G + (size_t)p * (640u * 640u * 16u) + cd;
    float ar = 0.0f, ai = 0.0f;
#pragma unroll
    for (int j1 = 0; j1 < JTAPS; j1++) {
        const float2* row = Gp + (size_t)s_ih[li][j1] * (640u * 16u);
        float w1 = s_wh[li][j1];
#pragma unroll
        for (int j2 = 0; j2 < JTAPS; j2++) {
            float2 v = row[s_iw[li][j2] * 16];
            float  w = w1 * s_ww[li][j2];
            ar = fmaf(v.x, w, ar);
            ai = fmaf(v.y, w, ai);
        }
    }
    float pr = s_pr[li], pi = s_pi[li];
    const float sc = 1.0f / 640.0f;               // ortho norm
    float2 o;
    o.x = (ar * pr - ai * pi) * sc;
    o.y = (ar * pi + ai * pr) * sc;
    out[(long)((p * NCOIL + cd) * KLEN) + l] = o;
}

// ---------------------------------------------------------------------------
// Launch
// ---------------------------------------------------------------------------
extern "C" void kernel_launch(void* const* d_in, const int* in_sizes, int n_in,
                              void* d_out, int out_size)
{
    const float2* image = (const float2*)d_in[0];   // (1,5,8,2,320,320,2)
    const float*  traj  = (const float*)d_in[1];    // (5,2,16000)

    float2 *Rp, *Gp;
    cudaGetSymbolAddress((void**)&Rp, g_R);
    cudaGetSymbolAddress((void**)&Gp, g_G);

    const int smem_bytes = (KOS + BUF_F2) * (int)sizeof(float2);   // 51200
    cudaFuncSetAttribute(fft640_kernel<1>,
                         cudaFuncAttributeMaxDynamicSharedMemorySize, smem_bytes);
    cudaFuncSetAttribute(fft640_kernel<2>,
                         cudaFuncAttributeMaxDynamicSharedMemorySize, smem_bytes);

    init_tables_kernel<<<3, 256>>>();

    // Stage 1: FFT along m (width), apodized.  cols = (p,c,n): 25600
    fft640_kernel<1><<<(PH * NCOIL * NIM) / 8, 256, smem_bytes>>>(image, Rp);

    // Stage 2: FFT along n (height).  cols = (p,q,c): 51200
    fft640_kernel<2><<<(PH * KOS * NCOIL) / 8, 256, smem_bytes>>>(Rp, Gp);

    // Stage 3: KB interpolation + recentering phase + ortho scale
    {
        dim3 grid(KLEN / 16, PH);
        interp_kernel<<<grid, 256>>>(traj, (float2*)d_out);
    }
}

// round 6
// speedup vs baseline: 1.1933x; 1.1933x over previous
#include <cuda_runtime.h>
#include <cuda_bf16.h>
#include <math.h>

// Problem constants
#define PH     5
#define NCOIL  16          // ch*d = 8*2
#define NIM    320         // H = W
#define KOS    640         // 2x oversampled grid
#define KLEN   16000
#define JTAPS  6
#define ALPHA_F 14.04f     // 2.34 * 6
#define PI_F   3.14159265358979323846f

// ---------------------------------------------------------------------------
// Static device scratch (no allocations allowed)
//   g_R: stage-1 out, layout [p][q][c][n]   (p<5, q<640, c<16, n<320)
//   g_G: stage-2 out, layout [p][k][q][c]   (coil innermost for interp)
// ---------------------------------------------------------------------------
__device__ float2 g_R[PH * KOS * NCOIL * NIM];      // 131 MB
__device__ float2 g_G[PH * KOS * KOS * NCOIL];      // 262 MB
__device__ float2 g_tw[KOS];                        // W640^t table
__device__ float  g_sh[NIM];                        // apodization (sh == sw)
__device__ float  g_inv_i0a;                        // 1 / I0(alpha)

// ---------------------------------------------------------------------------
// Compile-time twiddle tables (fold to FFMA immediates after full unroll)
// ---------------------------------------------------------------------------
__device__ constexpr float W5R[5] = {
    1.0f, 0.30901699437495f, -0.80901699437495f, -0.80901699437495f, 0.30901699437495f };
__device__ constexpr float W5I[5] = {
    0.0f, -0.95105651629515f, -0.58778525229247f, 0.58778525229247f, 0.95105651629515f };
__device__ constexpr float W20R[20] = {
    1.0f, 0.95105651629515f, 0.80901699437495f, 0.58778525229247f, 0.30901699437495f,
    0.0f, -0.30901699437495f, -0.58778525229247f, -0.80901699437495f, -0.95105651629515f,
    -1.0f, -0.95105651629515f, -0.80901699437495f, -0.58778525229247f, -0.30901699437495f,
    0.0f, 0.30901699437495f, 0.58778525229247f, 0.80901699437495f, 0.95105651629515f };
__device__ constexpr float W20I[20] = {
    0.0f, -0.30901699437495f, -0.58778525229247f, -0.80901699437495f, -0.95105651629515f,
    -1.0f, -0.95105651629515f, -0.80901699437495f, -0.58778525229247f, -0.30901699437495f,
    0.0f, 0.30901699437495f, 0.58778525229247f, 0.80901699437495f, 0.95105651629515f,
    1.0f, 0.95105651629515f, 0.80901699437495f, 0.58778525229247f, 0.30901699437495f };

// ---------------------------------------------------------------------------
// Modified Bessel I0 (Abramowitz & Stegun, rel err ~2e-7)
// ---------------------------------------------------------------------------
__device__ __forceinline__ float i0f_dev(float x) {
    if (x < 3.75f) {
        float t = x * (1.0f / 3.75f);
        t *= t;
        return 1.0f + t * (3.5156229f + t * (3.0899424f + t * (1.2067492f +
               t * (0.2659732f + t * (0.0360768f + t * 0.0045813f)))));
    } else {
        float t = 3.75f / x;
        float p = 0.39894228f + t * (0.01328592f + t * (0.00225319f +
                  t * (-0.00157565f + t * (0.00916281f + t * (-0.02057706f +
                  t * (0.02635537f + t * (-0.01647633f + t * 0.00392377f)))))));
        return p * expf(x) * rsqrtf(x);
    }
}

__global__ void init_tables_kernel() {
    int n = blockIdx.x * blockDim.x + threadIdx.x;   // 0..767
    if (n < NIM) {
        float i0a = i0f_dev(ALPHA_F);
        if (n == 0) g_inv_i0a = 1.0f / i0a;
        float nn = (float)(n - NIM / 2);
        float u  = nn * (1.0f / (float)KOS);
        float w  = PI_F * (float)JTAPS * u;
        float z2 = w * w - ALPHA_F * ALPHA_F;
        float z  = fmaxf(sqrtf(fabsf(z2)), 1e-6f);
        float core = (z2 > 0.0f) ? (sinf(z) / z) : (sinhf(z) / z);
        float ft = core * ((float)JTAPS / i0a);
        g_sh[n] = 1.0f / ft;
    }
    if (n < KOS) {
        float s, c;
        sincospif(-(float)n * (1.0f / 320.0f), &s, &c);
        g_tw[n] = make_float2(c, s);
    }
}

// ---------------------------------------------------------------------------
// Four-step 640-pt DFT of a zero-padded length-320 signal. Block = 256
// threads = 8 columns, warp = column, lane = n2.
//   n = 32*n1 + n2 (n1<20; nonzero n1<10),  k = k1 + 20*k2.
// Phase A (per lane, registers): 20-pt FFT over n1 as 4 x 5-pt DFTs +
//   constant-twiddle recombine; times W640^{n2 k1}.
// Phase B (fused, per k1): cross-lane 32-pt radix-2 DIF FFT via shfl_xor,
//   5 stages, per-lane stage twiddles hoisted. Output bit-reversed in lane.
// Phase C: scatter to smem at q = k1 + 20*bitrev5(lane).
// Phase D: coalesced global store.
// MODE 1: stage-1 (apodized, image -> R[p][q][c][n])
// MODE 2: stage-2 (R -> G[p][k][q][c])
// ---------------------------------------------------------------------------
#define SQ_PAD 9                       // buf row stride (8 cols + 1 pad)
#define BUF_F2 (KOS * SQ_PAD)          // 5760 float2

template <int MODE>
__global__ __launch_bounds__(256, 2) void fft640_kernel(
    const float2* __restrict__ in, float2* __restrict__ out)
{
    extern __shared__ float2 smem[];
    float2* tw  = smem;            // [640]
    float2* buf = smem + KOS;      // [BUF_F2], indexed buf[q*SQ_PAD + c]

    const int tid  = threadIdx.x;
    const int w    = tid >> 5;
    const int lane = tid & 31;

    for (int t = tid; t < KOS; t += 256) tw[t] = g_tw[t];
    __syncthreads();

    const int base_col = blockIdx.x * 8;
    const int col = base_col + w;

    // ---- load 10 inputs (coalesced: lane = n2), apodize in MODE 1 ----
    float xr[10], xi[10];
    {
        const float2* ip = in + (size_t)col * NIM + lane;
        float shr = 1.0f;
        if (MODE == 1) shr = g_sh[col % NIM];
#pragma unroll
        for (int n1 = 0; n1 < 10; n1++) {
            float2 v = ip[n1 * 32];
            if (MODE == 1) {
                float s = shr * g_sh[n1 * 32 + lane];
                v.x *= s; v.y *= s;
            }
            xr[n1] = v.x; xi[n1] = v.y;
        }
    }

    // ---- phase A part 1: four 5-pt DFTs over m of x[4m+r] (n1<10 nonzero) ----
    float f0r[5], f0i[5], f1r[5], f1i[5], f2r[5], f2i[5], f3r[5], f3i[5];
#pragma unroll
    for (int j = 0; j < 5; j++) {
        const int j2 = (2 * j) % 5;
        f0r[j] = xr[0] + (xr[4]*W5R[j] - xi[4]*W5I[j]) + (xr[8]*W5R[j2] - xi[8]*W5I[j2]);
        f0i[j] = xi[0] + (xr[4]*W5I[j] + xi[4]*W5R[j]) + (xr[8]*W5I[j2] + xi[8]*W5R[j2]);
        f1r[j] = xr[1] + (xr[5]*W5R[j] - xi[5]*W5I[j]) + (xr[9]*W5R[j2] - xi[9]*W5I[j2]);
        f1i[j] = xi[1] + (xr[5]*W5I[j] + xi[5]*W5R[j]) + (xr[9]*W5I[j2] + xi[9]*W5R[j2]);
        f2r[j] = xr[2] + (xr[6]*W5R[j] - xi[6]*W5I[j]);
        f2i[j] = xi[2] + (xr[6]*W5I[j] + xi[6]*W5R[j]);
        f3r[j] = xr[3] + (xr[7]*W5R[j] - xi[7]*W5I[j]);
        f3i[j] = xi[3] + (xr[7]*W5I[j] + xi[7]*W5R[j]);
    }

    // ---- hoisted per-lane state for phase B ----
    // DIF stage with span h: hi lanes (lane&h) compute (partner - mine) * W_{2h}^{lane mod h}
    const float2 ONE = make_float2(1.0f, 0.0f);
    const float2 T1 = (lane & 16) ? tw[20  * (lane & 15)] : ONE;   // W32^{lane%16}
    const float2 T2 = (lane & 8)  ? tw[40  * (lane & 7)]  : ONE;   // W16^{lane%8}
    const float2 T3 = (lane & 4)  ? tw[80  * (lane & 3)]  : ONE;   // W8^{lane%4}
    const float2 T4 = (lane & 2)  ? tw[160 * (lane & 1)]  : ONE;   // W4^{lane%2}
    const float s16 = (lane & 16) ? -1.0f : 1.0f;
    const float s8  = (lane & 8)  ? -1.0f : 1.0f;
    const float s4  = (lane & 4)  ? -1.0f : 1.0f;
    const float s2  = (lane & 2)  ? -1.0f : 1.0f;
    const float s1  = (lane & 1)  ? -1.0f : 1.0f;
    const int   br  = (int)(__brev((unsigned)lane) >> 27);         // bitrev5

#define BFLY(H, T, S)                                                   \
    do {                                                                \
        float ox = __shfl_xor_sync(0xffffffffu, vx, (H));               \
        float oy = __shfl_xor_sync(0xffffffffu, vy, (H));               \
        float tx = fmaf((S), vx, ox);                                   \
        float ty = fmaf((S), vy, oy);                                   \
        vx = tx * (T).x - ty * (T).y;                                   \
        vy = tx * (T).y + ty * (T).x;                                   \
    } while (0)

    // ---- phases A2+B+C fused per k1 ----
#pragma unroll
    for (int k = 0; k < 20; k++) {
        const int j = k % 5, ka = (2 * k) % 20, kb = (3 * k) % 20;
        float Xr = f0r[j]
            + (f1r[j]*W20R[k]  - f1i[j]*W20I[k])
            + (f2r[j]*W20R[ka] - f2i[j]*W20I[ka])
            + (f3r[j]*W20R[kb] - f3i[j]*W20I[kb]);
        float Xi = f0i[j]
            + (f1r[j]*W20I[k]  + f1i[j]*W20R[k])
            + (f2r[j]*W20I[ka] + f2i[j]*W20R[ka])
            + (f3r[j]*W20I[kb] + f3i[j]*W20R[kb]);
        float2 t6 = tw[lane * k];                // W640^{n2 k}
        float vx = Xr * t6.x - Xi * t6.y;
        float vy = Xr * t6.y + Xi * t6.x;

        BFLY(16, T1, s16);
        BFLY(8,  T2, s8);
        BFLY(4,  T3, s4);
        BFLY(2,  T4, s2);
        {   // last stage: twiddle = 1
            float ox = __shfl_xor_sync(0xffffffffu, vx, 1);
            float oy = __shfl_xor_sync(0xffffffffu, vy, 1);
            vx = fmaf(s1, vx, ox);
            vy = fmaf(s1, vy, oy);
        }
        // lane holds X[k2 = br]; q = k1 + 20*k2
        buf[(k + 20 * br) * SQ_PAD + w] = make_float2(vx, vy);
    }
#undef BFLY
    __syncthreads();

    // ---- phase D: coalesced global store ----
    size_t out_base; int stride_q;
    if (MODE == 1) {
        // col = (p*16+cc)*320 + n  ->  out[((p*640+q)*16+cc)*320 + n]
        int pc = base_col / NIM, n0 = base_col % NIM;
        int p = pc >> 4, cc = pc & 15;
        out_base = (size_t)p * (640u * 16u * 320u) + (size_t)cc * 320u + (size_t)n0;
        stride_q = 16 * 320;
    } else {
        // col = (p*640+qq)*16 + coil  ->  out[((p*640+k)*640+qq)*16 + coil]
        int pq = base_col >> 4, c0 = base_col & 15;
        int p = pq / KOS, qq = pq - p * KOS;
        out_base = (size_t)p * (640u * 640u * 16u) + (size_t)qq * 16u + (size_t)c0;
        stride_q = 640 * 16;
    }
#pragma unroll
    for (int i = 0; i < 20; i++) {
        int idx = i * 256 + tid;           // 0..5119
        int q = idx >> 3, c = idx & 7;
        out[out_base + (size_t)q * stride_q + c] = buf[q * SQ_PAD + c];
    }
}

// ---------------------------------------------------------------------------
// KB interpolation: 6x6 taps, 16 coils per point; G coil-innermost so the
// 16 coil-lanes read 128B contiguous per tap.
// ---------------------------------------------------------------------------
__global__ __launch_bounds__(256) void interp_kernel(
    const float* __restrict__ traj, float2* __restrict__ out)
{
    __shared__ float s_wh[16][JTAPS], s_ww[16][JTAPS];
    __shared__ int   s_ih[16][JTAPS], s_iw[16][JTAPS];
    __shared__ float s_pr[16], s_pi[16];

    const int tid = threadIdx.x;
    const int cd  = tid & 15;                     // coil
    const int li  = tid >> 4;                     // point within block
    const int p   = blockIdx.y;
    const int l   = blockIdx.x * 16 + li;

    const float inv_i0a = g_inv_i0a;

    if (cd < 2) {
        float om = traj[(long)(p * 2 + cd) * KLEN + l];
        float t  = om * (320.0f / PI_F);
        float base = floorf(t - 3.0f);
#pragma unroll
        for (int j = 0; j < JTAPS; j++) {
            float kf  = base + (float)(j + 1);
            float u   = t - kf;
            float ua  = u * (1.0f / 3.0f);
            float arg = fmaxf(1.0f - ua * ua, 0.0f);
            float w   = i0f_dev(ALPHA_F * sqrtf(arg)) * inv_i0a;
            int ki  = (int)kf;
            int idx = ki % KOS; if (idx < 0) idx += KOS;
            if (cd == 0) { s_wh[li][j] = w; s_ih[li][j] = idx; }
            else         { s_ww[li][j] = w; s_iw[li][j] = idx; }
        }
        if (cd == 0) {
            float om1 = traj[(long)(p * 2 + 1) * KLEN + l];
            float th  = 160.0f * (om + om1);
            float sp, cp;
            sincosf(th, &sp, &cp);
            s_pr[li] = cp; s_pi[li] = sp;
        }
    }
    __syncthreads();

    const float2* Gp = g_G + (size_t)p * (640u * 640u * 16u) + cd;
    float ar = 0.0f, ai = 0.0f;
#pragma unroll
    for (int j1 = 0; j1 < JTAPS; j1++) {
        const float2* row = Gp + (size_t)s_ih[li][j1] * (640u * 16u);
        float w1 = s_wh[li][j1];
#pragma unroll
        for (int j2 = 0; j2 < JTAPS; j2++) {
            float2 v = row[s_iw[li][j2] * 16];
            float  w = w1 * s_ww[li][j2];
            ar = fmaf(v.x, w, ar);
            ai = fmaf(v.y, w, ai);
        }
    }
    float pr = s_pr[li], pi = s_pi[li];
    const float sc = 1.0f / 640.0f;               // ortho norm
    float2 o;
    o.x = (ar * pr - ai * pi) * sc;
    o.y = (ar * pi + ai * pr) * sc;
    out[(long)((p * NCOIL + cd) * KLEN) + l] = o;
}

// ---------------------------------------------------------------------------
// Launch
// ---------------------------------------------------------------------------
extern "C" void kernel_launch(void* const* d_in, const int* in_sizes, int n_in,
                              void* d_out, int out_size)
{
    const float2* image = (const float2*)d_in[0];   // (1,5,8,2,320,320,2)
    const float*  traj  = (const float*)d_in[1];    // (5,2,16000)

    float2 *Rp, *Gp;
    cudaGetSymbolAddress((void**)&Rp, g_R);
    cudaGetSymbolAddress((void**)&Gp, g_G);

    const int smem_bytes = (KOS + BUF_F2) * (int)sizeof(float2);   // 51200
    cudaFuncSetAttribute(fft640_kernel<1>,
                         cudaFuncAttributeMaxDynamicSharedMemorySize, smem_bytes);
    cudaFuncSetAttribute(fft640_kernel<2>,
                         cudaFuncAttributeMaxDynamicSharedMemorySize, smem_bytes);

    init_tables_kernel<<<3, 256>>>();

    // Stage 1: FFT along m (width), apodized.  cols = (p,c,n): 25600
    fft640_kernel<1><<<(PH * NCOIL * NIM) / 8, 256, smem_bytes>>>(image, Rp);

    // Stage 2: FFT along n (height).  cols = (p,q,c): 51200
    fft640_kernel<2><<<(PH * KOS * NCOIL) / 8, 256, smem_bytes>>>(Rp, Gp);

    // Stage 3: KB interpolation + recentering phase + ortho scale
    {
        dim3 grid(KLEN / 16, PH);
        interp_kernel<<<grid, 256>>>(traj, (float2*)d_out);
    }
}

// round 7
// speedup vs baseline: 1.3419x; 1.1245x over previous
#include <cuda_runtime.h>
#include <cuda_bf16.h>
#include <cuda_fp16.h>
#include <math.h>

// Problem constants
#define PH     5
#define NCOIL  16          // ch*d = 8*2
#define NIM    320         // H = W
#define KOS    640         // 2x oversampled grid
#define KLEN   16000
#define JTAPS  6
#define ALPHA_F 14.04f     // 2.34 * 6
#define PI_F   3.14159265358979323846f

// ---------------------------------------------------------------------------
// Static device scratch (no allocations allowed)
//   g_R : stage-1 out fp32, layout [p][q][c][n]
//   g_Gh: stage-2 out fp16, layout [p][k][q][c] (coil innermost for interp)
// ---------------------------------------------------------------------------
__device__ float2  g_R [PH * KOS * NCOIL * NIM];     // 131 MB
__device__ __half2 g_Gh[PH * KOS * KOS * NCOIL];     // 131 MB
__device__ float2  g_tw[KOS];                        // W640^t table
__device__ float   g_sh[NIM];                        // apodization (sh == sw)
__device__ float   g_inv_i0a;                        // 1 / I0(alpha)

// ---------------------------------------------------------------------------
// Packed f32x2 helpers (sm_103a packed fp32 pipe; PTX-only, ptxas won't fuse)
// ---------------------------------------------------------------------------
typedef unsigned long long u2;

__device__ __forceinline__ u2 pk2(float lo, float hi) {
    u2 r; asm("mov.b64 %0, {%1, %2};" : "=l"(r) : "f"(lo), "f"(hi)); return r;
}
__device__ __forceinline__ void upk2(float& lo, float& hi, u2 v) {
    asm("mov.b64 {%0, %1}, %2;" : "=f"(lo), "=f"(hi) : "l"(v));
}
__device__ __forceinline__ u2 dup2(float x) { return pk2(x, x); }
__device__ __forceinline__ u2 swap2(u2 v) {
    float a, b; upk2(a, b, v); return pk2(b, a);
}
__device__ __forceinline__ u2 fma2(u2 a, u2 b, u2 c) {
    u2 d; asm("fma.rn.f32x2 %0, %1, %2, %3;" : "=l"(d) : "l"(a), "l"(b), "l"(c)); return d;
}
__device__ __forceinline__ u2 mul2(u2 a, u2 b) {
    u2 d; asm("mul.rn.f32x2 %0, %1, %2;" : "=l"(d) : "l"(a), "l"(b)); return d;
}
// acc += z * (wr + i wi), z packed (re,im), zs = swap2(z)
#define CFMA(acc, z, zs, wr, wi)                            \
    do {                                                    \
        acc = fma2((z),  dup2(wr), acc);                    \
        acc = fma2((zs), pk2(-(wi), (wi)), acc);            \
    } while (0)

// ---------------------------------------------------------------------------
// Compile-time twiddle tables
// ---------------------------------------------------------------------------
__device__ constexpr float W5R[5] = {
    1.0f, 0.30901699437495f, -0.80901699437495f, -0.80901699437495f, 0.30901699437495f };
__device__ constexpr float W5I[5] = {
    0.0f, -0.95105651629515f, -0.58778525229247f, 0.58778525229247f, 0.95105651629515f };
__device__ constexpr float W20R[20] = {
    1.0f, 0.95105651629515f, 0.80901699437495f, 0.58778525229247f, 0.30901699437495f,
    0.0f, -0.30901699437495f, -0.58778525229247f, -0.80901699437495f, -0.95105651629515f,
    -1.0f, -0.95105651629515f, -0.80901699437495f, -0.58778525229247f, -0.30901699437495f,
    0.0f, 0.30901699437495f, 0.58778525229247f, 0.80901699437495f, 0.95105651629515f };
__device__ constexpr float W20I[20] = {
    0.0f, -0.30901699437495f, -0.58778525229247f, -0.80901699437495f, -0.95105651629515f,
    -1.0f, -0.95105651629515f, -0.80901699437495f, -0.58778525229247f, -0.30901699437495f,
    0.0f, 0.30901699437495f, 0.58778525229247f, 0.80901699437495f, 0.95105651629515f,
    1.0f, 0.95105651629515f, 0.80901699437495f, 0.58778525229247f, 0.30901699437495f };

// ---------------------------------------------------------------------------
// Modified Bessel I0 (Abramowitz & Stegun, rel err ~2e-7)
// ---------------------------------------------------------------------------
__device__ __forceinline__ float i0f_dev(float x) {
    if (x < 3.75f) {
        float t = x * (1.0f / 3.75f);
        t *= t;
        return 1.0f + t * (3.5156229f + t * (3.0899424f + t * (1.2067492f +
               t * (0.2659732f + t * (0.0360768f + t * 0.0045813f)))));
    } else {
        float t = 3.75f / x;
        float p = 0.39894228f + t * (0.01328592f + t * (0.00225319f +
                  t * (-0.00157565f + t * (0.00916281f + t * (-0.02057706f +
                  t * (0.02635537f + t * (-0.01647633f + t * 0.00392377f)))))));
        return p * expf(x) * rsqrtf(x);
    }
}

__global__ void init_tables_kernel() {
    int n = blockIdx.x * blockDim.x + threadIdx.x;
    if (n < NIM) {
        float i0a = i0f_dev(ALPHA_F);
        if (n == 0) g_inv_i0a = 1.0f / i0a;
        float nn = (float)(n - NIM / 2);
        float u  = nn * (1.0f / (float)KOS);
        float w  = PI_F * (float)JTAPS * u;
        float z2 = w * w - ALPHA_F * ALPHA_F;
        float z  = fmaxf(sqrtf(fabsf(z2)), 1e-6f);
        float core = (z2 > 0.0f) ? (sinf(z) / z) : (sinhf(z) / z);
        float ft = core * ((float)JTAPS / i0a);
        g_sh[n] = 1.0f / ft;
    }
    if (n < KOS) {
        float s, c;
        sincospif(-(float)n * (1.0f / 320.0f), &s, &c);
        g_tw[n] = make_float2(c, s);
    }
}

// ---------------------------------------------------------------------------
// Four-step 640-pt DFT of a zero-padded length-320 signal. Block = 256
// threads = 8 columns, warp = column, lane = n2. All complex math in
// packed f32x2 (fma.rn.f32x2).
//   n = 32*n1 + n2 (n1<20; nonzero n1<10),  k = k1 + 20*k2.
// Phase A: 20-pt FFT over n1 (4 x 5-pt + constant recombine), * W640^{n2 k1}.
// Phase B: cross-lane 32-pt radix-2 DIF FFT via shfl_xor (output bitrev lane).
// Phase C: scatter to smem at q = k1 + 20*bitrev5(lane).
// Phase D: coalesced global store (MODE 1: fp32 R; MODE 2: fp16 G).
// ---------------------------------------------------------------------------
#define SQ_PAD 9                       // buf row stride (8 cols + 1 pad)
#define BUF_F2 (KOS * SQ_PAD)          // 5760 float2

template <int MODE>
__global__ __launch_bounds__(256, 2) void fft640_kernel(
    const float2* __restrict__ in, void* __restrict__ outv)
{
    extern __shared__ float2 smem[];
    float2* tw  = smem;            // [640]
    float2* buf = smem + KOS;      // [BUF_F2], indexed buf[q*SQ_PAD + c]

    const int tid  = threadIdx.x;
    const int w    = tid >> 5;
    const int lane = tid & 31;

    for (int t = tid; t < KOS; t += 256) tw[t] = g_tw[t];
    __syncthreads();

    const int base_col = blockIdx.x * 8;
    const int col = base_col + w;

    // ---- load 10 inputs (coalesced: lane = n2), apodize in MODE 1 ----
    u2 xz[10], xs[10];
    {
        const float2* ip = in + (size_t)col * NIM + lane;
        float shr = 1.0f;
        if (MODE == 1) shr = g_sh[col % NIM];
#pragma unroll
        for (int n1 = 0; n1 < 10; n1++) {
            float2 v = ip[n1 * 32];
            if (MODE == 1) {
                float s = shr * g_sh[n1 * 32 + lane];
                v.x *= s; v.y *= s;
            }
            xz[n1] = pk2(v.x, v.y);
            xs[n1] = pk2(v.y, v.x);
        }
    }

    // ---- phase A1: four 5-pt DFTs over m of x[4m+r] (n1<10 nonzero) ----
    u2 F0[5], F1[5], F2[5], F3[5];
#pragma unroll
    for (int j = 0; j < 5; j++) {
        const int j2 = (2 * j) % 5;
        u2 f0 = xz[0], f1 = xz[1], f2 = xz[2], f3 = xz[3];
        CFMA(f0, xz[4], xs[4], W5R[j],  W5I[j]);
        CFMA(f0, xz[8], xs[8], W5R[j2], W5I[j2]);
        CFMA(f1, xz[5], xs[5], W5R[j],  W5I[j]);
        CFMA(f1, xz[9], xs[9], W5R[j2], W5I[j2]);
        CFMA(f2, xz[6], xs[6], W5R[j],  W5I[j]);
        CFMA(f3, xz[7], xs[7], W5R[j],  W5I[j]);
        F0[j] = f0; F1[j] = f1; F2[j] = f2; F3[j] = f3;
    }

    // ---- hoisted per-lane butterfly state ----
    const float2 ONE = make_float2(1.0f, 0.0f);
    const float2 T1f = (lane & 16) ? tw[20  * (lane & 15)] : ONE;   // W32^{lane%16}
    const float2 T2f = (lane & 8)  ? tw[40  * (lane & 7)]  : ONE;   // W16^{lane%8}
    const float2 T3f = (lane & 4)  ? tw[80  * (lane & 3)]  : ONE;   // W8^{lane%4}
    const float2 T4f = (lane & 2)  ? tw[160 * (lane & 1)]  : ONE;   // W4^{lane%2}
    const u2 T1c = dup2(T1f.x), T1s = pk2(-T1f.y, T1f.y);
    const u2 T2c = dup2(T2f.x), T2s = pk2(-T2f.y, T2f.y);
    const u2 T3c = dup2(T3f.x), T3s = pk2(-T3f.y, T3f.y);
    const u2 T4c = dup2(T4f.x), T4s = pk2(-T4f.y, T4f.y);
    const u2 S16 = dup2((lane & 16) ? -1.0f : 1.0f);
    const u2 S8  = dup2((lane & 8)  ? -1.0f : 1.0f);
    const u2 S4  = dup2((lane & 4)  ? -1.0f : 1.0f);
    const u2 S2  = dup2((lane & 2)  ? -1.0f : 1.0f);
    const u2 S1  = dup2((lane & 1)  ? -1.0f : 1.0f);
    const int br = (int)(__brev((unsigned)lane) >> 27);            // bitrev5

#define BFLY2(H, TC, TS, SD)                                            \
    do {                                                                \
        float vx_, vy_;                                                 \
        upk2(vx_, vy_, v);                                              \
        float ox_ = __shfl_xor_sync(0xffffffffu, vx_, (H));             \
        float oy_ = __shfl_xor_sync(0xffffffffu, vy_, (H));             \
        u2 t_ = fma2((SD), v, pk2(ox_, oy_));                           \
        v = mul2(t_, (TC));                                             \
        v = fma2(swap2(t_), (TS), v);                                   \
    } while (0)

    // ---- phases A2+B+C fused per k1 ----
#pragma unroll
    for (int k = 0; k < 20; k++) {
        const int j = k % 5, ka = (2 * k) % 20, kb = (3 * k) % 20;
        u2 X = F0[j];
        CFMA(X, F1[j], swap2(F1[j]), W20R[k],  W20I[k]);
        CFMA(X, F2[j], swap2(F2[j]), W20R[ka], W20I[ka]);
        CFMA(X, F3[j], swap2(F3[j]), W20R[kb], W20I[kb]);
        // twiddle by W640^{n2 k}
        float2 t6 = tw[lane * k];
        u2 v = mul2(X, dup2(t6.x));
        v = fma2(swap2(X), pk2(-t6.y, t6.y), v);

        BFLY2(16, T1c, T1s, S16);
        BFLY2(8,  T2c, T2s, S8);
        BFLY2(4,  T3c, T3s, S4);
        BFLY2(2,  T4c, T4s, S2);
        {   // last stage: twiddle = 1
            float vx_, vy_;
            upk2(vx_, vy_, v);
            float ox_ = __shfl_xor_sync(0xffffffffu, vx_, 1);
            float oy_ = __shfl_xor_sync(0xffffffffu, vy_, 1);
            v = fma2(S1, v, pk2(ox_, oy_));
        }
        // lane holds X[k2 = br]; q = k1 + 20*k2
        ((u2*)buf)[(k + 20 * br) * SQ_PAD + w] = v;
    }
#undef BFLY2
    __syncthreads();

    // ---- phase D: coalesced global store ----
    if (MODE == 1) {
        // col = (p*16+cc)*320 + n  ->  out[((p*640+q)*16+cc)*320 + n]
        float2* out = (float2*)outv;
        int pc = base_col / NIM, n0 = base_col % NIM;
        int p = pc >> 4, cc = pc & 15;
        size_t out_base = (size_t)p * (640u * 16u * 320u) + (size_t)cc * 320u + (size_t)n0;
#pragma unroll
        for (int i = 0; i < 20; i++) {
            int idx = i * 256 + tid;
            int q = idx >> 3, c = idx & 7;
            out[out_base + (size_t)q * (16 * 320) + c] = buf[q * SQ_PAD + c];
        }
    } else {
        // col = (p*640+qq)*16 + coil  ->  out[((p*640+k)*640+qq)*16 + coil]
        __half2* out = (__half2*)outv;
        int pq = base_col >> 4, c0 = base_col & 15;
        int p = pq / KOS, qq = pq - p * KOS;
        size_t out_base = (size_t)p * (640u * 640u * 16u) + (size_t)qq * 16u + (size_t)c0;
#pragma unroll
        for (int i = 0; i < 20; i++) {
            int idx = i * 256 + tid;
            int q = idx >> 3, c = idx & 7;
            out[out_base + (size_t)q * (640 * 16) + c] =
                __float22half2_rn(buf[q * SQ_PAD + c]);
        }
    }
}

// ---------------------------------------------------------------------------
// KB interpolation: 6x6 taps, 16 coils per point; G fp16 coil-innermost so
// the 16 coil-lanes read 64B contiguous per tap.
// ---------------------------------------------------------------------------
__global__ __launch_bounds__(256) void interp_kernel(
    const float* __restrict__ traj, float2* __restrict__ out)
{
    __shared__ float s_wh[16][JTAPS], s_ww[16][JTAPS];
    __shared__ int   s_ih[16][JTAPS], s_iw[16][JTAPS];
    __shared__ float s_pr[16], s_pi[16];

    const int tid = threadIdx.x;
    const int cd  = tid & 15;                     // coil
    const int li  = tid >> 4;                     // point within block
    const int p   = blockIdx.y;
    const int l   = blockIdx.x * 16 + li;

    const float inv_i0a = g_inv_i0a;

    if (cd < 2) {
        float om = traj[(long)(p * 2 + cd) * KLEN + l];
        float t  = om * (320.0f / PI_F);
        float base = floorf(t - 3.0f);
#pragma unroll
        for (int j = 0; j < JTAPS; j++) {
            float kf  = base + (float)(j + 1);
            float u   = t - kf;
            float ua  = u * (1.0f / 3.0f);
            float arg = fmaxf(1.0f - ua * ua, 0.0f);
            float w   = i0f_dev(ALPHA_F * sqrtf(arg)) * inv_i0a;
            int ki  = (int)kf;
            int idx = ki % KOS; if (idx < 0) idx += KOS;
            if (cd == 0) { s_wh[li][j] = w; s_ih[li][j] = idx; }
            else         { s_ww[li][j] = w; s_iw[li][j] = idx; }
        }
        if (cd == 0) {
            float om1 = traj[(long)(p * 2 + 1) * KLEN + l];
            float th  = 160.0f * (om + om1);
            float sp, cp;
            sincosf(th, &sp, &cp);
            s_pr[li] = cp; s_pi[li] = sp;
        }
    }
    __syncthreads();

    const __half2* Gp = g_Gh + (size_t)p * (640u * 640u * 16u) + cd;
    float ar = 0.0f, ai = 0.0f;
#pragma unroll
    for (int j1 = 0; j1 < JTAPS; j1++) {
        const __half2* row = Gp + (size_t)s_ih[li][j1] * (640u * 16u);
        float w1 = s_wh[li][j1];
#pragma unroll
        for (int j2 = 0; j2 < JTAPS; j2++) {
            float2 v = __half22float2(row[s_iw[li][j2] * 16]);
            float  w = w1 * s_ww[li][j2];
            ar = fmaf(v.x, w, ar);
            ai = fmaf(v.y, w, ai);
        }
    }
    float pr = s_pr[li], pi = s_pi[li];
    const float sc = 1.0f / 640.0f;               // ortho norm
    float2 o;
    o.x = (ar * pr - ai * pi) * sc;
    o.y = (ar * pi + ai * pr) * sc;
    out[(long)((p * NCOIL + cd) * KLEN) + l] = o;
}

// ---------------------------------------------------------------------------
// Launch
// ---------------------------------------------------------------------------
extern "C" void kernel_launch(void* const* d_in, const int* in_sizes, int n_in,
                              void* d_out, int out_size)
{
    const float2* image = (const float2*)d_in[0];   // (1,5,8,2,320,320,2)
    const float*  traj  = (const float*)d_in[1];    // (5,2,16000)

    float2 *Rp; __half2 *Ghp;
    cudaGetSymbolAddress((void**)&Rp,  g_R);
    cudaGetSymbolAddress((void**)&Ghp, g_Gh);

    const int smem_bytes = (KOS + BUF_F2) * (int)sizeof(float2);   // 51200
    cudaFuncSetAttribute(fft640_kernel<1>,
                         cudaFuncAttributeMaxDynamicSharedMemorySize, smem_bytes);
    cudaFuncSetAttribute(fft640_kernel<2>,
                         cudaFuncAttributeMaxDynamicSharedMemorySize, smem_bytes);

    init_tables_kernel<<<3, 256>>>();

    // Stage 1: FFT along m (width), apodized.  cols = (p,c,n): 25600
    fft640_kernel<1><<<(PH * NCOIL * NIM) / 8, 256, smem_bytes>>>(image, (void*)Rp);

    // Stage 2: FFT along n (height).  cols = (p,q,c): 51200
    fft640_kernel<2><<<(PH * KOS * NCOIL) / 8, 256, smem_bytes>>>(Rp, (void*)Ghp);

    // Stage 3: KB interpolation + recentering phase + ortho scale
    {
        dim3 grid(KLEN / 16, PH);
        interp_kernel<<<grid, 256>>>(traj, (float2*)d_out);
    }
}

// round 8
// speedup vs baseline: 2.0577x; 1.5335x over previous
#include <cuda_runtime.h>
#include <cuda_bf16.h>
#include <cuda_fp16.h>
#include <math.h>

// Problem constants
#define PH     5
#define NCOIL  16          // ch*d = 8*2
#define NIM    320         // H = W
#define KOS    640         // 2x oversampled grid
#define KLEN   16000
#define JTAPS  6
#define ALPHA_F 14.04f     // 2.34 * 6
#define PI_F   3.14159265358979323846f

// ---------------------------------------------------------------------------
// Static device scratch (no allocations allowed)
//   g_R : stage-1 out fp32, layout [p][q][c][n]
//   g_Gh: stage-2 out fp16, layout [p][k][q][c] (coil innermost for interp)
// ---------------------------------------------------------------------------
__device__ float2  g_R [PH * KOS * NCOIL * NIM];     // 131 MB
__device__ __half2 g_Gh[PH * KOS * KOS * NCOIL];     // 131 MB
__device__ float   g_sh[NIM];                        // apodization (sh == sw)
__device__ float   g_inv_i0a;                        // 1 / I0(alpha)

// ---------------------------------------------------------------------------
// Packed f32x2 helpers (sm_103a packed fp32 pipe; PTX-only)
// ---------------------------------------------------------------------------
typedef unsigned long long u2;

__device__ __forceinline__ u2 pk2(float lo, float hi) {
    u2 r; asm("mov.b64 %0, {%1, %2};" : "=l"(r) : "f"(lo), "f"(hi)); return r;
}
__device__ __forceinline__ void upk2(float& lo, float& hi, u2 v) {
    asm("mov.b64 {%0, %1}, %2;" : "=f"(lo), "=f"(hi) : "l"(v));
}
__device__ __forceinline__ u2 dup2(float x) { return pk2(x, x); }
__device__ __forceinline__ u2 swap2(u2 v) {
    float a, b; upk2(a, b, v); return pk2(b, a);
}
__device__ __forceinline__ u2 fma2(u2 a, u2 b, u2 c) {
    u2 d; asm("fma.rn.f32x2 %0, %1, %2, %3;" : "=l"(d) : "l"(a), "l"(b), "l"(c)); return d;
}
__device__ __forceinline__ u2 mul2(u2 a, u2 b) {
    u2 d; asm("mul.rn.f32x2 %0, %1, %2;" : "=l"(d) : "l"(a), "l"(b)); return d;
}
// acc += z * (wr + i wi), z packed (re,im)
#define CFMA(acc, z, wr, wi)                                \
    do {                                                    \
        acc = fma2((z),        dup2(wr), acc);              \
        acc = fma2(swap2(z), pk2(-(wi), (wi)), acc);        \
    } while (0)

// complex mult: a * b where b = (bc dup, bs = (-si, si))
__device__ __forceinline__ u2 cmul(u2 a, u2 bc, u2 bs) {
    return fma2(swap2(a), bs, mul2(a, bc));
}

// ---------------------------------------------------------------------------
// Compile-time twiddle tables
// ---------------------------------------------------------------------------
__device__ constexpr float W5R[5] = {
    1.0f, 0.30901699437495f, -0.80901699437495f, -0.80901699437495f, 0.30901699437495f };
__device__ constexpr float W5I[5] = {
    0.0f, -0.95105651629515f, -0.58778525229247f, 0.58778525229247f, 0.95105651629515f };
__device__ constexpr float W20R[20] = {
    1.0f, 0.95105651629515f, 0.80901699437495f, 0.58778525229247f, 0.30901699437495f,
    0.0f, -0.30901699437495f, -0.58778525229247f, -0.80901699437495f, -0.95105651629515f,
    -1.0f, -0.95105651629515f, -0.80901699437495f, -0.58778525229247f, -0.30901699437495f,
    0.0f, 0.30901699437495f, 0.58778525229247f, 0.80901699437495f, 0.95105651629515f };
__device__ constexpr float W20I[20] = {
    0.0f, -0.30901699437495f, -0.58778525229247f, -0.80901699437495f, -0.95105651629515f,
    -1.0f, -0.95105651629515f, -0.80901699437495f, -0.58778525229247f, -0.30901699437495f,
    0.0f, 0.30901699437495f, 0.58778525229247f, 0.80901699437495f, 0.95105651629515f,
    1.0f, 0.95105651629515f, 0.80901699437495f, 0.58778525229247f, 0.30901699437495f };

// ---------------------------------------------------------------------------
// Modified Bessel I0 (Abramowitz & Stegun, rel err ~2e-7)
// ---------------------------------------------------------------------------
__device__ __forceinline__ float i0f_dev(float x) {
    if (x < 3.75f) {
        float t = x * (1.0f / 3.75f);
        t *= t;
        return 1.0f + t * (3.5156229f + t * (3.0899424f + t * (1.2067492f +
               t * (0.2659732f + t * (0.0360768f + t * 0.0045813f)))));
    } else {
        float t = 3.75f / x;
        float p = 0.39894228f + t * (0.01328592f + t * (0.00225319f +
                  t * (-0.00157565f + t * (0.00916281f + t * (-0.02057706f +
                  t * (0.02635537f + t * (-0.01647633f + t * 0.00392377f)))))));
        return p * expf(x) * rsqrtf(x);
    }
}

__global__ void init_tables_kernel() {
    int n = blockIdx.x * blockDim.x + threadIdx.x;
    if (n < NIM) {
        float i0a = i0f_dev(ALPHA_F);
        if (n == 0) g_inv_i0a = 1.0f / i0a;
        float nn = (float)(n - NIM / 2);
        float u  = nn * (1.0f / (float)KOS);
        float w  = PI_F * (float)JTAPS * u;
        float z2 = w * w - ALPHA_F * ALPHA_F;
        float z  = fmaxf(sqrtf(fabsf(z2)), 1e-6f);
        float core = (z2 > 0.0f) ? (sinf(z) / z) : (sinhf(z) / z);
        float ft = core * ((float)JTAPS / i0a);
        g_sh[n] = 1.0f / ft;
    }
}

// ---------------------------------------------------------------------------
// Four-step 640-pt DFT of a zero-padded length-320 signal. Block = 256
// threads = 8 columns, warp = column, lane = n2. Packed f32x2 math.
//   n = 32*n1 + n2 (n1<20; nonzero n1<10),  k = k1 + 20*k2.
// Phase A: 20-pt FFT over n1 (4 x 5-pt + constant recombine); twiddle
//   W640^{n2 k1} generated iteratively (no table, no LDS).
// Phase B: cross-lane 32-pt radix-2 DIF FFT via shfl_xor; per-lane stage
//   twiddles computed once via sincospif. Output bit-reversed in lane.
// Phase C: store to smem at loc = k1*32 + k2 (low-conflict layout).
// Phase D: remapped coalesced global store (MODE 1: fp32 R; MODE 2: fp16 G).
// ---------------------------------------------------------------------------
#define SQ_PAD 9                       // buf row stride (8 cols + 1 pad)
#define BUF_U2 (KOS * SQ_PAD)          // 5760 u2 = 46080 B

template <int MODE>
__global__ __launch_bounds__(256, 2) void fft640_kernel(
    const float2* __restrict__ in, void* __restrict__ outv)
{
    extern __shared__ u2 buf[];        // [BUF_U2], buf[loc*SQ_PAD + c]

    const int tid  = threadIdx.x;
    const int w    = tid >> 5;
    const int lane = tid & 31;

    const int base_col = blockIdx.x * 8;
    const int col = base_col + w;

    // ---- load 10 inputs (coalesced: lane = n2), apodize in MODE 1 ----
    u2 xz[10];
    {
        const float2* ip = in + (size_t)col * NIM + lane;
        float shr = 1.0f;
        if (MODE == 1) shr = g_sh[col % NIM];
#pragma unroll
        for (int n1 = 0; n1 < 10; n1++) {
            float2 v = ip[n1 * 32];
            if (MODE == 1) {
                float s = shr * g_sh[n1 * 32 + lane];
                v.x *= s; v.y *= s;
            }
            xz[n1] = pk2(v.x, v.y);
        }
    }

    // ---- phase A1: four 5-pt DFTs over m of x[4m+r] (n1<10 nonzero) ----
    u2 F0[5], F1[5], F2[5], F3[5];
#pragma unroll
    for (int j = 0; j < 5; j++) {
        const int j2 = (2 * j) % 5;
        u2 f0 = xz[0], f1 = xz[1], f2 = xz[2], f3 = xz[3];
        CFMA(f0, xz[4], W5R[j],  W5I[j]);
        CFMA(f0, xz[8], W5R[j2], W5I[j2]);
        CFMA(f1, xz[5], W5R[j],  W5I[j]);
        CFMA(f1, xz[9], W5R[j2], W5I[j2]);
        CFMA(f2, xz[6], W5R[j],  W5I[j]);
        CFMA(f3, xz[7], W5R[j],  W5I[j]);
        F0[j] = f0; F1[j] = f1; F2[j] = f2; F3[j] = f3;
    }

    // ---- per-lane twiddles (computed, no table) ----
    float sc_s, sc_c;
    // butterfly stage twiddles
    sincospif(-(float)(lane & 15) * (1.0f / 16.0f), &sc_s, &sc_c);
    const u2 T1c = dup2((lane & 16) ? sc_c : 1.0f);
    const u2 T1s = (lane & 16) ? pk2(-sc_s, sc_s) : pk2(0.0f, 0.0f);
    sincospif(-(float)(lane & 7) * (1.0f / 8.0f), &sc_s, &sc_c);
    const u2 T2c = dup2((lane & 8) ? sc_c : 1.0f);
    const u2 T2s = (lane & 8) ? pk2(-sc_s, sc_s) : pk2(0.0f, 0.0f);
    sincospif(-(float)(lane & 3) * (1.0f / 4.0f), &sc_s, &sc_c);
    const u2 T3c = dup2((lane & 4) ? sc_c : 1.0f);
    const u2 T3s = (lane & 4) ? pk2(-sc_s, sc_s) : pk2(0.0f, 0.0f);
    // W4^{lane&1} = 1 or -i
    const bool t4rot = (lane & 2) && (lane & 1);
    const u2 T4c = dup2(t4rot ? 0.0f : 1.0f);
    const u2 T4s = t4rot ? pk2(1.0f, -1.0f) : pk2(0.0f, 0.0f);   // *(-i): (x,y)->(y,-x)
    const u2 S16 = dup2((lane & 16) ? -1.0f : 1.0f);
    const u2 S8  = dup2((lane & 8)  ? -1.0f : 1.0f);
    const u2 S4  = dup2((lane & 4)  ? -1.0f : 1.0f);
    const u2 S2  = dup2((lane & 2)  ? -1.0f : 1.0f);
    const u2 S1  = dup2((lane & 1)  ? -1.0f : 1.0f);
    const int br = (int)(__brev((unsigned)lane) >> 27);           // bitrev5

    // W640^lane step for iterative twiddle
    sincospif(-(float)lane * (1.0f / 320.0f), &sc_s, &sc_c);
    const u2 wstep_c = dup2(sc_c);
    const u2 wstep_s = pk2(-sc_s, sc_s);
    u2 wacc_c = dup2(1.0f), wacc_s = pk2(0.0f, 0.0f);   // (cos dup, (-sin,sin))

#define BFLY2(H, TC, TS, SD)                                            \
    do {                                                                \
        float vx_, vy_;                                                 \
        upk2(vx_, vy_, v);                                              \
        float ox_ = __shfl_xor_sync(0xffffffffu, vx_, (H));             \
        float oy_ = __shfl_xor_sync(0xffffffffu, vy_, (H));             \
        u2 t_ = fma2((SD), v, pk2(ox_, oy_));                           \
        v = cmul(t_, (TC), (TS));                                       \
    } while (0)

    // ---- phases A2+B+C fused per k1 ----
#pragma unroll
    for (int k = 0; k < 20; k++) {
        const int j = k % 5, ka = (2 * k) % 20, kb = (3 * k) % 20;
        u2 X = F0[j];
        CFMA(X, F1[j], W20R[k],  W20I[k]);
        CFMA(X, F2[j], W20R[ka], W20I[ka]);
        CFMA(X, F3[j], W20R[kb], W20I[kb]);
        // twiddle by W640^{n2 k} (iteratively generated)
        u2 v = cmul(X, wacc_c, wacc_s);
        // advance wacc = wacc * wstep  (complex: c' = cc*sc - ss*ss-part)
        {
            float ac, as_;
            float dc, ds_;
            upk2(ac, ac, wacc_c);          // ac = cosA (dup)
            upk2(ds_, as_, wacc_s);        // as_ = sinA (hi), ds_ = -sinA
            upk2(dc, dc, wstep_c);         // dc = cosB
            float sb; float dummy;
            upk2(dummy, sb, wstep_s);      // sb = sinB
            float nc = ac * dc - as_ * sb; // cos(A+B)
            float ns = as_ * dc + ac * sb; // sin(A+B)
            wacc_c = dup2(nc);
            wacc_s = pk2(-ns, ns);
        }

        BFLY2(16, T1c, T1s, S16);
        BFLY2(8,  T2c, T2s, S8);
        BFLY2(4,  T3c, T3s, S4);
        BFLY2(2,  T4c, T4s, S2);
        {   // last stage: twiddle = 1
            float vx_, vy_;
            upk2(vx_, vy_, v);
            float ox_ = __shfl_xor_sync(0xffffffffu, vx_, 1);
            float oy_ = __shfl_xor_sync(0xffffffffu, vy_, 1);
            v = fma2(S1, v, pk2(ox_, oy_));
        }
        // lane holds X[k2 = br]; store at loc = k*32 + br (low-conflict)
        buf[(k * 32 + br) * SQ_PAD + w] = v;
    }
#undef BFLY2
    __syncthreads();

    // ---- phase D: remapped coalesced global store ----
    // thread -> (k2 = tid>>3, c = tid&7); loop over k1. q = k1 + 20*k2.
    const int k2 = tid >> 3;
    const int c  = tid & 7;
    if (MODE == 1) {
        // col = (p*16+cc)*320 + n  ->  out[((p*640+q)*16+cc)*320 + n]
        float2* out = (float2*)outv;
        int pc = base_col / NIM, n0 = base_col % NIM;
        int p = pc >> 4, cc = pc & 15;
        size_t out_base = (size_t)p * (640u * 16u * 320u) + (size_t)cc * 320u
                        + (size_t)n0 + c;
#pragma unroll
        for (int k1 = 0; k1 < 20; k1++) {
            u2 v = buf[(k1 * 32 + k2) * SQ_PAD + c];
            float vx, vy; upk2(vx, vy, v);
            out[out_base + (size_t)(k1 + 20 * k2) * (16 * 320)] = make_float2(vx, vy);
        }
    } else {
        // col = (p*640+qq)*16 + coil  ->  out[((p*640+kk)*640+qq)*16 + coil]
        __half2* out = (__half2*)outv;
        int pq = base_col >> 4, c0 = base_col & 15;
        int p = pq / KOS, qq = pq - p * KOS;
        size_t out_base = (size_t)p * (640u * 640u * 16u) + (size_t)qq * 16u
                        + (size_t)c0 + c;
#pragma unroll
        for (int k1 = 0; k1 < 20; k1++) {
            u2 v = buf[(k1 * 32 + k2) * SQ_PAD + c];
            float vx, vy; upk2(vx, vy, v);
            out[out_base + (size_t)(k1 + 20 * k2) * (640 * 16)] =
                __float22half2_rn(make_float2(vx, vy));
        }
    }
}

// ---------------------------------------------------------------------------
// KB interpolation: 6x6 taps, 16 coils per point; G fp16 coil-innermost so
// the 16 coil-lanes read 64B contiguous per tap.
// ---------------------------------------------------------------------------
__global__ __launch_bounds__(256) void interp_kernel(
    const float* __restrict__ traj, float2* __restrict__ out)
{
    __shared__ float s_wh[16][JTAPS], s_ww[16][JTAPS];
    __shared__ int   s_ih[16][JTAPS], s_iw[16][JTAPS];
    __shared__ float s_pr[16], s_pi[16];

    const int tid = threadIdx.x;
    const int cd  = tid & 15;                     // coil
    const int li  = tid >> 4;                     // point within block
    const int p   = blockIdx.y;
    const int l   = blockIdx.x * 16 + li;

    const float inv_i0a = g_inv_i0a;

    if (cd < 2) {
        float om = traj[(long)(p * 2 + cd) * KLEN + l];
        float t  = om * (320.0f / PI_F);
        float base = floorf(t - 3.0f);
#pragma unroll
        for (int j = 0; j < JTAPS; j++) {
            float kf  = base + (float)(j + 1);
            float u   = t - kf;
            float ua  = u * (1.0f / 3.0f);
            float arg = fmaxf(1.0f - ua * ua, 0.0f);
            float w   = i0f_dev(ALPHA_F * sqrtf(arg)) * inv_i0a;
            int ki  = (int)kf;
            int idx = ki % KOS; if (idx < 0) idx += KOS;
            if (cd == 0) { s_wh[li][j] = w; s_ih[li][j] = idx; }
            else         { s_ww[li][j] = w; s_iw[li][j] = idx; }
        }
        if (cd == 0) {
            float om1 = traj[(long)(p * 2 + 1) * KLEN + l];
            float th  = 160.0f * (om + om1);
            float sp, cp;
            sincosf(th, &sp, &cp);
            s_pr[li] = cp; s_pi[li] = sp;
        }
    }
    __syncthreads();

    const __half2* Gp = g_Gh + (size_t)p * (640u * 640u * 16u) + cd;
    float ar = 0.0f, ai = 0.0f;
#pragma unroll
    for (int j1 = 0; j1 < JTAPS; j1++) {
        const __half2* row = Gp + (size_t)s_ih[li][j1] * (640u * 16u);
        float w1 = s_wh[li][j1];
#pragma unroll
        for (int j2 = 0; j2 < JTAPS; j2++) {
            float2 v = __half22float2(row[s_iw[li][j2] * 16]);
            float  w = w1 * s_ww[li][j2];
            ar = fmaf(v.x, w, ar);
            ai = fmaf(v.y, w, ai);
        }
    }
    float pr = s_pr[li], pi = s_pi[li];
    const float sc = 1.0f / 640.0f;               // ortho norm
    float2 o;
    o.x = (ar * pr - ai * pi) * sc;
    o.y = (ar * pi + ai * pr) * sc;
    out[(long)((p * NCOIL + cd) * KLEN) + l] = o;
}

// ---------------------------------------------------------------------------
// Launch
// ---------------------------------------------------------------------------
extern "C" void kernel_launch(void* const* d_in, const int* in_sizes, int n_in,
                              void* d_out, int out_size)
{
    const float2* image = (const float2*)d_in[0];   // (1,5,8,2,320,320,2)
    const float*  traj  = (const float*)d_in[1];    // (5,2,16000)

    float2 *Rp; __half2 *Ghp;
    cudaGetSymbolAddress((void**)&Rp,  g_R);
    cudaGetSymbolAddress((void**)&Ghp, g_Gh);

    const int smem_bytes = BUF_U2 * (int)sizeof(u2);   // 46080
    cudaFuncSetAttribute(fft640_kernel<1>,
                         cudaFuncAttributeMaxDynamicSharedMemorySize, smem_bytes);
    cudaFuncSetAttribute(fft640_kernel<2>,
                         cudaFuncAttributeMaxDynamicSharedMemorySize, smem_bytes);

    init_tables_kernel<<<2, 256>>>();

    // Stage 1: FFT along m (width), apodized.  cols = (p,c,n): 25600
    fft640_kernel<1><<<(PH * NCOIL * NIM) / 8, 256, smem_bytes>>>(image, (void*)Rp);

    // Stage 2: FFT along n (height).  cols = (p,q,c): 51200
    fft640_kernel<2><<<(PH * KOS * NCOIL) / 8, 256, smem_bytes>>>(Rp, (void*)Ghp);

    // Stage 3: KB interpolation + recentering phase + ortho scale
    {
        dim3 grid(KLEN / 16, PH);
        interp_kernel<<<grid, 256>>>(traj, (float2*)d_out);
    }
}

// round 9
// speedup vs baseline: 2.1476x; 1.0437x over previous
#include <cuda_runtime.h>
#include <cuda_bf16.h>
#include <cuda_fp16.h>
#include <math.h>

// Problem constants
#define PH     5
#define NCOIL  16          // ch*d = 8*2
#define NIM    320         // H = W
#define KOS    640         // 2x oversampled grid
#define KLEN   16000
#define JTAPS  6
#define ALPHA_F 14.04f     // 2.34 * 6
#define PI_F   3.14159265358979323846f

// ---------------------------------------------------------------------------
// Static device scratch (no allocations allowed)
//   g_Rh: stage-1 out fp16, layout [p][q][c][n]  (fits in 126MB L2!)
//   g_Gh: stage-2 out fp16, layout [p][k][q][c]  (coil innermost for interp)
// ---------------------------------------------------------------------------
__device__ __half2 g_Rh[PH * KOS * NCOIL * NIM];     // 65.5 MB
__device__ __half2 g_Gh[PH * KOS * KOS * NCOIL];     // 131 MB
__device__ float   g_sh[NIM];                        // apodization (sh == sw)
__device__ float   g_inv_i0a;                        // 1 / I0(alpha)

// ---------------------------------------------------------------------------
// Packed f32x2 helpers (sm_103a packed fp32 pipe; PTX-only)
// ---------------------------------------------------------------------------
typedef unsigned long long u2;

__device__ __forceinline__ u2 pk2(float lo, float hi) {
    u2 r; asm("mov.b64 %0, {%1, %2};" : "=l"(r) : "f"(lo), "f"(hi)); return r;
}
__device__ __forceinline__ void upk2(float& lo, float& hi, u2 v) {
    asm("mov.b64 {%0, %1}, %2;" : "=f"(lo), "=f"(hi) : "l"(v));
}
__device__ __forceinline__ u2 dup2(float x) { return pk2(x, x); }
__device__ __forceinline__ u2 swap2(u2 v) {
    float a, b; upk2(a, b, v); return pk2(b, a);
}
__device__ __forceinline__ u2 fma2(u2 a, u2 b, u2 c) {
    u2 d; asm("fma.rn.f32x2 %0, %1, %2, %3;" : "=l"(d) : "l"(a), "l"(b), "l"(c)); return d;
}
__device__ __forceinline__ u2 mul2(u2 a, u2 b) {
    u2 d; asm("mul.rn.f32x2 %0, %1, %2;" : "=l"(d) : "l"(a), "l"(b)); return d;
}
// acc += z * (wr + i wi), z packed (re,im)
#define CFMA(acc, z, wr, wi)                                \
    do {                                                    \
        acc = fma2((z),        dup2(wr), acc);              \
        acc = fma2(swap2(z), pk2(-(wi), (wi)), acc);        \
    } while (0)

// complex mult: a * b where b = (bc dup, bs = (-si, si))
__device__ __forceinline__ u2 cmul(u2 a, u2 bc, u2 bs) {
    return fma2(swap2(a), bs, mul2(a, bc));
}

// ---------------------------------------------------------------------------
// Compile-time twiddle tables
// ---------------------------------------------------------------------------
__device__ constexpr float W5R[5] = {
    1.0f, 0.30901699437495f, -0.80901699437495f, -0.80901699437495f, 0.30901699437495f };
__device__ constexpr float W5I[5] = {
    0.0f, -0.95105651629515f, -0.58778525229247f, 0.58778525229247f, 0.95105651629515f };
__device__ constexpr float W20R[20] = {
    1.0f, 0.95105651629515f, 0.80901699437495f, 0.58778525229247f, 0.30901699437495f,
    0.0f, -0.30901699437495f, -0.58778525229247f, -0.80901699437495f, -0.95105651629515f,
    -1.0f, -0.95105651629515f, -0.80901699437495f, -0.58778525229247f, -0.30901699437495f,
    0.0f, 0.30901699437495f, 0.58778525229247f, 0.80901699437495f, 0.95105651629515f };
__device__ constexpr float W20I[20] = {
    0.0f, -0.30901699437495f, -0.58778525229247f, -0.80901699437495f, -0.95105651629515f,
    -1.0f, -0.95105651629515f, -0.80901699437495f, -0.58778525229247f, -0.30901699437495f,
    0.0f, 0.30901699437495f, 0.58778525229247f, 0.80901699437495f, 0.95105651629515f,
    1.0f, 0.95105651629515f, 0.80901699437495f, 0.58778525229247f, 0.30901699437495f };

// ---------------------------------------------------------------------------
// Modified Bessel I0 (Abramowitz & Stegun, rel err ~2e-7)
// ---------------------------------------------------------------------------
__device__ __forceinline__ float i0f_dev(float x) {
    if (x < 3.75f) {
        float t = x * (1.0f / 3.75f);
        t *= t;
        return 1.0f + t * (3.5156229f + t * (3.0899424f + t * (1.2067492f +
               t * (0.2659732f + t * (0.0360768f + t * 0.0045813f)))));
    } else {
        float t = 3.75f / x;
        float p = 0.39894228f + t * (0.01328592f + t * (0.00225319f +
                  t * (-0.00157565f + t * (0.00916281f + t * (-0.02057706f +
                  t * (0.02635537f + t * (-0.01647633f + t * 0.00392377f)))))));
        return p * expf(x) * rsqrtf(x);
    }
}

__global__ void init_tables_kernel() {
    int n = blockIdx.x * blockDim.x + threadIdx.x;
    if (n < NIM) {
        float i0a = i0f_dev(ALPHA_F);
        if (n == 0) g_inv_i0a = 1.0f / i0a;
        float nn = (float)(n - NIM / 2);
        float u  = nn * (1.0f / (float)KOS);
        float w  = PI_F * (float)JTAPS * u;
        float z2 = w * w - ALPHA_F * ALPHA_F;
        float z  = fmaxf(sqrtf(fabsf(z2)), 1e-6f);
        float core = (z2 > 0.0f) ? (sinf(z) / z) : (sinhf(z) / z);
        float ft = core * ((float)JTAPS / i0a);
        g_sh[n] = 1.0f / ft;
    }
}

// ---------------------------------------------------------------------------
// Four-step 640-pt DFT of a zero-padded length-320 signal. Block = 256
// threads = 8 columns, warp = column, lane = n2. Packed f32x2 math.
//   n = 32*n1 + n2 (n1<20; nonzero n1<10),  k = k1 + 20*k2.
// Phase A: 20-pt FFT over n1 (4 x 5-pt + constant recombine); twiddle
//   W640^{n2 k1} generated iteratively (no table, no LDS).
// Phase B: cross-lane 32-pt radix-2 DIF FFT via shfl_xor; per-lane stage
//   twiddles computed once via sincospif. Output bit-reversed in lane.
// Phase C: store to smem at loc = k1*32 + k2 (low-conflict layout).
// Phase D: remapped coalesced global store (fp16).
// MODE 1: in = fp32 image (apodized) -> g_Rh.  MODE 2: in = g_Rh -> g_Gh.
// ---------------------------------------------------------------------------
#define SQ_PAD 9                       // buf row stride (8 cols + 1 pad)
#define BUF_U2 (KOS * SQ_PAD)          // 5760 u2 = 46080 B

template <int MODE>
__global__ __launch_bounds__(256, 2) void fft640_kernel(
    const void* __restrict__ inv, __half2* __restrict__ out)
{
    extern __shared__ u2 buf[];        // [BUF_U2], buf[loc*SQ_PAD + c]

    const int tid  = threadIdx.x;
    const int w    = tid >> 5;
    const int lane = tid & 31;

    const int base_col = blockIdx.x * 8;
    const int col = base_col + w;

    // ---- load 10 inputs (coalesced: lane = n2), apodize in MODE 1 ----
    u2 xz[10];
    if (MODE == 1) {
        const float2* ip = (const float2*)inv + (size_t)col * NIM + lane;
        float shr = g_sh[col % NIM];
#pragma unroll
        for (int n1 = 0; n1 < 10; n1++) {
            float2 v = ip[n1 * 32];
            float s = shr * g_sh[n1 * 32 + lane];
            xz[n1] = pk2(v.x * s, v.y * s);
        }
    } else {
        const __half2* ip = (const __half2*)inv + (size_t)col * NIM + lane;
#pragma unroll
        for (int n1 = 0; n1 < 10; n1++) {
            float2 v = __half22float2(ip[n1 * 32]);
            xz[n1] = pk2(v.x, v.y);
        }
    }

    // ---- phase A1: four 5-pt DFTs over m of x[4m+r] (n1<10 nonzero) ----
    u2 F0[5], F1[5], F2[5], F3[5];
#pragma unroll
    for (int j = 0; j < 5; j++) {
        const int j2 = (2 * j) % 5;
        u2 f0 = xz[0], f1 = xz[1], f2 = xz[2], f3 = xz[3];
        CFMA(f0, xz[4], W5R[j],  W5I[j]);
        CFMA(f0, xz[8], W5R[j2], W5I[j2]);
        CFMA(f1, xz[5], W5R[j],  W5I[j]);
        CFMA(f1, xz[9], W5R[j2], W5I[j2]);
        CFMA(f2, xz[6], W5R[j],  W5I[j]);
        CFMA(f3, xz[7], W5R[j],  W5I[j]);
        F0[j] = f0; F1[j] = f1; F2[j] = f2; F3[j] = f3;
    }

    // ---- per-lane twiddles (computed, no table) ----
    float sc_s, sc_c;
    sincospif(-(float)(lane & 15) * (1.0f / 16.0f), &sc_s, &sc_c);
    const u2 T1c = dup2((lane & 16) ? sc_c : 1.0f);
    const u2 T1s = (lane & 16) ? pk2(-sc_s, sc_s) : pk2(0.0f, 0.0f);
    sincospif(-(float)(lane & 7) * (1.0f / 8.0f), &sc_s, &sc_c);
    const u2 T2c = dup2((lane & 8) ? sc_c : 1.0f);
    const u2 T2s = (lane & 8) ? pk2(-sc_s, sc_s) : pk2(0.0f, 0.0f);
    sincospif(-(float)(lane & 3) * (1.0f / 4.0f), &sc_s, &sc_c);
    const u2 T3c = dup2((lane & 4) ? sc_c : 1.0f);
    const u2 T3s = (lane & 4) ? pk2(-sc_s, sc_s) : pk2(0.0f, 0.0f);
    const bool t4rot = (lane & 2) && (lane & 1);
    const u2 T4c = dup2(t4rot ? 0.0f : 1.0f);
    const u2 T4s = t4rot ? pk2(1.0f, -1.0f) : pk2(0.0f, 0.0f);   // *(-i)
    const u2 S16 = dup2((lane & 16) ? -1.0f : 1.0f);
    const u2 S8  = dup2((lane & 8)  ? -1.0f : 1.0f);
    const u2 S4  = dup2((lane & 4)  ? -1.0f : 1.0f);
    const u2 S2  = dup2((lane & 2)  ? -1.0f : 1.0f);
    const u2 S1  = dup2((lane & 1)  ? -1.0f : 1.0f);
    const int br = (int)(__brev((unsigned)lane) >> 27);          // bitrev5

    // W640^lane step for iterative twiddle
    sincospif(-(float)lane * (1.0f / 320.0f), &sc_s, &sc_c);
    const u2 wstep_c = dup2(sc_c);
    const u2 wstep_s = pk2(-sc_s, sc_s);
    u2 wacc_c = dup2(1.0f), wacc_s = pk2(0.0f, 0.0f);

#define BFLY2(H, TC, TS, SD)                                            \
    do {                                                                \
        float vx_, vy_;                                                 \
        upk2(vx_, vy_, v);                                              \
        float ox_ = __shfl_xor_sync(0xffffffffu, vx_, (H));             \
        float oy_ = __shfl_xor_sync(0xffffffffu, vy_, (H));             \
        u2 t_ = fma2((SD), v, pk2(ox_, oy_));                           \
        v = cmul(t_, (TC), (TS));                                       \
    } while (0)

    // ---- phases A2+B+C fused per k1 ----
#pragma unroll
    for (int k = 0; k < 20; k++) {
        const int j = k % 5, ka = (2 * k) % 20, kb = (3 * k) % 20;
        u2 X = F0[j];
        CFMA(X, F1[j], W20R[k],  W20I[k]);
        CFMA(X, F2[j], W20R[ka], W20I[ka]);
        CFMA(X, F3[j], W20R[kb], W20I[kb]);
        // twiddle by W640^{n2 k} (iteratively generated)
        u2 v = cmul(X, wacc_c, wacc_s);
        {
            float ac, as_, dc, sb, dummy;
            upk2(ac, ac, wacc_c);
            upk2(dummy, as_, wacc_s);
            upk2(dc, dc, wstep_c);
            upk2(dummy, sb, wstep_s);
            float nc = ac * dc - as_ * sb;
            float ns = as_ * dc + ac * sb;
            wacc_c = dup2(nc);
            wacc_s = pk2(-ns, ns);
        }

        BFLY2(16, T1c, T1s, S16);
        BFLY2(8,  T2c, T2s, S8);
        BFLY2(4,  T3c, T3s, S4);
        BFLY2(2,  T4c, T4s, S2);
        {   // last stage: twiddle = 1
            float vx_, vy_;
            upk2(vx_, vy_, v);
            float ox_ = __shfl_xor_sync(0xffffffffu, vx_, 1);
            float oy_ = __shfl_xor_sync(0xffffffffu, vy_, 1);
            v = fma2(S1, v, pk2(ox_, oy_));
        }
        buf[(k * 32 + br) * SQ_PAD + w] = v;
    }
#undef BFLY2
    __syncthreads();

    // ---- phase D: remapped coalesced fp16 global store ----
    // thread -> (k2 = tid>>3, c = tid&7); loop over k1. q = k1 + 20*k2.
    const int k2 = tid >> 3;
    const int c  = tid & 7;
    size_t out_base; int stride_q;
    if (MODE == 1) {
        // col = (p*16+cc)*320 + n  ->  out[((p*640+q)*16+cc)*320 + n]
        int pc = base_col / NIM, n0 = base_col % NIM;
        int p = pc >> 4, cc = pc & 15;
        out_base = (size_t)p * (640u * 16u * 320u) + (size_t)cc * 320u
                 + (size_t)n0 + c;
        stride_q = 16 * 320;
    } else {
        // col = (p*640+qq)*16 + coil  ->  out[((p*640+kk)*640+qq)*16 + coil]
        int pq = base_col >> 4, c0 = base_col & 15;
        int p = pq / KOS, qq = pq - p * KOS;
        out_base = (size_t)p * (640u * 640u * 16u) + (size_t)qq * 16u
                 + (size_t)c0 + c;
        stride_q = 640 * 16;
    }
#pragma unroll
    for (int k1 = 0; k1 < 20; k1++) {
        u2 v = buf[(k1 * 32 + k2) * SQ_PAD + c];
        float vx, vy; upk2(vx, vy, v);
        out[out_base + (size_t)(k1 + 20 * k2) * stride_q] =
            __float22half2_rn(make_float2(vx, vy));
    }
}

// ---------------------------------------------------------------------------
// KB interpolation: 6x6 taps, 16 coils per point; G fp16 coil-innermost so
// the 16 coil-lanes read 64B contiguous per tap. Weights/indices cached in
// registers (smem broadcast reads once, then pure register FMA).
// ---------------------------------------------------------------------------
__global__ __launch_bounds__(256) void interp_kernel(
    const float* __restrict__ traj, float2* __restrict__ out)
{
    __shared__ float s_wh[16][JTAPS], s_ww[16][JTAPS];
    __shared__ int   s_ih[16][JTAPS], s_iw[16][JTAPS];
    __shared__ float s_pr[16], s_pi[16];

    const int tid = threadIdx.x;
    const int cd  = tid & 15;                     // coil
    const int li  = tid >> 4;                     // point within block
    const int p   = blockIdx.y;
    const int l   = blockIdx.x * 16 + li;

    const float inv_i0a = g_inv_i0a;

    if (cd < 2) {
        float om = traj[(long)(p * 2 + cd) * KLEN + l];
        float t  = om * (320.0f / PI_F);
        float base = floorf(t - 3.0f);
#pragma unroll
        for (int j = 0; j < JTAPS; j++) {
            float kf  = base + (float)(j + 1);
            float u   = t - kf;
            float ua  = u * (1.0f / 3.0f);
            float arg = fmaxf(1.0f - ua * ua, 0.0f);
            float w   = i0f_dev(ALPHA_F * sqrtf(arg)) * inv_i0a;
            int ki  = (int)kf;
            int idx = ki % KOS; if (idx < 0) idx += KOS;
            if (cd == 0) { s_wh[li][j] = w; s_ih[li][j] = idx; }
            else         { s_ww[li][j] = w; s_iw[li][j] = idx; }
        }
        if (cd == 0) {
            float om1 = traj[(long)(p * 2 + 1) * KLEN + l];
            float th  = 160.0f * (om + om1);
            float sp, cp;
            sincosf(th, &sp, &cp);
            s_pr[li] = cp; s_pi[li] = sp;
        }
    }
    __syncthreads();

    // cache weights/indices in registers (broadcast LDS, once)
    float wh[JTAPS], ww[JTAPS];
    int   ihx[JTAPS], iwx[JTAPS];
#pragma unroll
    for (int j = 0; j < JTAPS; j++) {
        wh[j]  = s_wh[li][j];
        ww[j]  = s_ww[li][j];
        ihx[j] = s_ih[li][j];
        iwx[j] = s_iw[li][j] * 16;
    }
    const float pr = s_pr[li], pi = s_pi[li];

    const __half2* Gp = g_Gh + (size_t)p * (640u * 640u * 16u) + cd;
    float ar = 0.0f, ai = 0.0f;
#pragma unroll
    for (int j1 = 0; j1 < JTAPS; j1++) {
        const __half2* row = Gp + (size_t)ihx[j1] * (640u * 16u);
        const float w1 = wh[j1];
#pragma unroll
        for (int j2 = 0; j2 < JTAPS; j2++) {
            float2 v = __half22float2(row[iwx[j2]]);
            float  w = w1 * ww[j2];
            ar = fmaf(v.x, w, ar);
            ai = fmaf(v.y, w, ai);
        }
    }
    const float sc = 1.0f / 640.0f;               // ortho norm
    float2 o;
    o.x = (ar * pr - ai * pi) * sc;
    o.y = (ar * pi + ai * pr) * sc;
    out[(long)((p * NCOIL + cd) * KLEN) + l] = o;
}

// ---------------------------------------------------------------------------
// Launch
// ---------------------------------------------------------------------------
extern "C" void kernel_launch(void* const* d_in, const int* in_sizes, int n_in,
                              void* d_out, int out_size)
{
    const float2* image = (const float2*)d_in[0];   // (1,5,8,2,320,320,2)
    const float*  traj  = (const float*)d_in[1];    // (5,2,16000)

    __half2 *Rhp, *Ghp;
    cudaGetSymbolAddress((void**)&Rhp, g_Rh);
    cudaGetSymbolAddress((void**)&Ghp, g_Gh);

    const int smem_bytes = BUF_U2 * (int)sizeof(u2);   // 46080
    cudaFuncSetAttribute(fft640_kernel<1>,
                         cudaFuncAttributeMaxDynamicSharedMemorySize, smem_bytes);
    cudaFuncSetAttribute(fft640_kernel<2>,
                         cudaFuncAttributeMaxDynamicSharedMemorySize, smem_bytes);

    init_tables_kernel<<<2, 256>>>();

    // Stage 1: FFT along m (width), apodized.  cols = (p,c,n): 25600
    fft640_kernel<1><<<(PH * NCOIL * NIM) / 8, 256, smem_bytes>>>(
        (const void*)image, Rhp);

    // Stage 2: FFT along n (height).  cols = (p,q,c): 51200  (R reads hit L2)
    fft640_kernel<2><<<(PH * KOS * NCOIL) / 8, 256, smem_bytes>>>(
        (const void*)Rhp, Ghp);

    // Stage 3: KB interpolation + recentering phase + ortho scale
    {
        dim3 grid(KLEN / 16, PH);
        interp_kernel<<<grid, 256>>>(traj, (float2*)d_out);
    }
}

// round 11
// speedup vs baseline: 2.1524x; 1.0022x over previous
#include <cuda_runtime.h>
#include <cuda_bf16.h>
#include <cuda_fp16.h>
#include <math.h>

// Problem constants
#define PH     5
#define NCOIL  16          // ch*d = 8*2
#define NIM    320         // H = W
#define KOS    640         // 2x oversampled grid
#define KLEN   16000
#define JTAPS  6
#define ALPHA_F 14.04f     // 2.34 * 6
#define PI_F   3.14159265358979323846f

// ---------------------------------------------------------------------------
// Static device scratch (no allocations allowed)
//   g_Rh: stage-1 out fp16, layout [p][q][c][n]  (L2-resident, 65.5 MB)
//   g_Gh: stage-2 out fp16, layout [p][k][q][c]  (coil innermost for interp)
// ---------------------------------------------------------------------------
__device__ __half2 g_Rh[PH * KOS * NCOIL * NIM];     // 65.5 MB
__device__ __half2 g_Gh[PH * KOS * KOS * NCOIL];     // 131 MB
__device__ float   g_sh[NIM];                        // apodization (sh == sw)
__device__ float   g_inv_i0a;                        // 1 / I0(alpha)

// ---------------------------------------------------------------------------
// Packed f32x2 helpers. In the FFT below, one u2 holds the SAME component
// (re or im) of TWO columns: v_re = (colA.re, colB.re).
// ---------------------------------------------------------------------------
typedef unsigned long long u2;

__device__ __forceinline__ u2 pk2(float lo, float hi) {
    u2 r; asm("mov.b64 %0, {%1, %2};" : "=l"(r) : "f"(lo), "f"(hi)); return r;
}
__device__ __forceinline__ void upk2(float& lo, float& hi, u2 v) {
    asm("mov.b64 {%0, %1}, %2;" : "=f"(lo), "=f"(hi) : "l"(v));
}
__device__ __forceinline__ u2 dup2(float x) { return pk2(x, x); }
__device__ __forceinline__ u2 fma2(u2 a, u2 b, u2 c) {
    u2 d; asm("fma.rn.f32x2 %0, %1, %2, %3;" : "=l"(d) : "l"(a), "l"(b), "l"(c)); return d;
}
__device__ __forceinline__ u2 mul2(u2 a, u2 b) {
    u2 d; asm("mul.rn.f32x2 %0, %1, %2;" : "=l"(d) : "l"(a), "l"(b)); return d;
}
__device__ __forceinline__ u2 add2(u2 a, u2 b) {
    u2 d; asm("add.rn.f32x2 %0, %1, %2;" : "=l"(d) : "l"(a), "l"(b)); return d;
}

// (Xr,Xi) += (zr,zi) * (wr + i wi), wr/wi compile-time: branches fold.
__device__ __forceinline__ void cfma_ri(u2& Xr, u2& Xi, u2 zr, u2 zi,
                                        float wr, float wi) {
    if (wi == 0.0f) {
        if (wr == 1.0f)       { Xr = add2(Xr, zr); Xi = add2(Xi, zi); }
        else                  { Xr = fma2(zr, dup2(wr), Xr); Xi = fma2(zi, dup2(wr), Xi); }
    } else if (wr == 0.0f)    { Xr = fma2(zi, dup2(-wi), Xr); Xi = fma2(zr, dup2(wi), Xi); }
    else {
        Xr = fma2(zr, dup2(wr), Xr); Xr = fma2(zi, dup2(-wi), Xr);
        Xi = fma2(zr, dup2(wi), Xi); Xi = fma2(zi, dup2(wr), Xi);
    }
}

// ---------------------------------------------------------------------------
// Compile-time twiddle tables
// ---------------------------------------------------------------------------
__device__ constexpr float W5R[5] = {
    1.0f, 0.30901699437495f, -0.80901699437495f, -0.80901699437495f, 0.30901699437495f };
__device__ constexpr float W5I[5] = {
    0.0f, -0.95105651629515f, -0.58778525229247f, 0.58778525229247f, 0.95105651629515f };
__device__ constexpr float W20R[20] = {
    1.0f, 0.95105651629515f, 0.80901699437495f, 0.58778525229247f, 0.30901699437495f,
    0.0f, -0.30901699437495f, -0.58778525229247f, -0.80901699437495f, -0.95105651629515f,
    -1.0f, -0.95105651629515f, -0.80901699437495f, -0.58778525229247f, -0.30901699437495f,
    0.0f, 0.30901699437495f, 0.58778525229247f, 0.80901699437495f, 0.95105651629515f };
__device__ constexpr float W20I[20] = {
    0.0f, -0.30901699437495f, -0.58778525229247f, -0.80901699437495f, -0.95105651629515f,
    -1.0f, -0.95105651629515f, -0.80901699437495f, -0.58778525229247f, -0.30901699437495f,
    0.0f, 0.30901699437495f, 0.58778525229247f, 0.80901699437495f, 0.95105651629515f,
    1.0f, 0.95105651629515f, 0.80901699437495f, 0.58778525229247f, 0.30901699437495f };

// ---------------------------------------------------------------------------
// Modified Bessel I0 (Abramowitz & Stegun, rel err ~2e-7)
// ---------------------------------------------------------------------------
__device__ __forceinline__ float i0f_dev(float x) {
    if (x < 3.75f) {
        float t = x * (1.0f / 3.75f);
        t *= t;
        return 1.0f + t * (3.5156229f + t * (3.0899424f + t * (1.2067492f +
               t * (0.2659732f + t * (0.0360768f + t * 0.0045813f)))));
    } else {
        float t = 3.75f / x;
        float p = 0.39894228f + t * (0.01328592f + t * (0.00225319f +
                  t * (-0.00157565f + t * (0.00916281f + t * (-0.02057706f +
                  t * (0.02635537f + t * (-0.01647633f + t * 0.00392377f)))))));
        return p * expf(x) * rsqrtf(x);
    }
}

__global__ void init_tables_kernel() {
    int n = blockIdx.x * blockDim.x + threadIdx.x;
    if (n < NIM) {
        float i0a = i0f_dev(ALPHA_F);
        if (n == 0) g_inv_i0a = 1.0f / i0a;
        float nn = (float)(n - NIM / 2);
        float u  = nn * (1.0f / (float)KOS);
        float w  = PI_F * (float)JTAPS * u;
        float z2 = w * w - ALPHA_F * ALPHA_F;
        float z  = fmaxf(sqrtf(fabsf(z2)), 1e-6f);
        float core = (z2 > 0.0f) ? (sinf(z) / z) : (sinhf(z) / z);
        float ft = core * ((float)JTAPS / i0a);
        g_sh[n] = 1.0f / ft;
    }
}

// ---------------------------------------------------------------------------
// Four-step 640-pt DFT, zero-padded length-320 input. Block = 128 threads
// = 4 warps; EACH WARP PROCESSES 2 COLUMNS (re/im plane packing: one u2
// holds a component of both columns; all twiddle math shared).
//   n = 32*n1 + n2 (n1<20; nonzero n1<10),  k = k1 + 20*k2.
// Outer loop j=0..4: recompute the four 5-pt DFT outputs F0..F3[j] from xz,
// then the 4 outputs k = j+5t; W640^{n2 k} via two iterative chains
// (step W640^{n2} across j, step W640^{5 n2} across t).
// Phase B: cross-lane 32-pt radix-2 DIF FFT via 64-bit shfl_xor.
// Phase C: smem at loc = k1*32 + k2 (low-conflict). Phase D: coalesced fp16.
// MODE 1: in = fp32 image (apodized) -> g_Rh.  MODE 2: in = g_Rh -> g_Gh.
// ---------------------------------------------------------------------------
#define SQ_PAD 9                       // buf row stride (8 cols + 1 pad)
#define BUF_U2 (KOS * SQ_PAD)          // 5760 u2 = 46080 B

template <int MODE>
__global__ __launch_bounds__(128, 4) void fft640_kernel(
    const void* __restrict__ inv, __half2* __restrict__ out)
{
    extern __shared__ u2 buf[];        // [BUF_U2], buf[loc*SQ_PAD + c]

    const int tid  = threadIdx.x;
    const int w    = tid >> 5;         // warp 0..3
    const int lane = tid & 31;

    const int base_col = blockIdx.x * 8;
    const int colA = base_col + 2 * w;
    const int colB = colA + 1;

    // ---- load 10 inputs x 2 cols (coalesced: lane = n2), apodize MODE 1 ----
    u2 xr[10], xi[10];
    if (MODE == 1) {
        const float2* ipA = (const float2*)inv + (size_t)colA * NIM + lane;
        const float2* ipB = (const float2*)inv + (size_t)colB * NIM + lane;
        float shrA = g_sh[colA % NIM];
        float shrB = g_sh[colB % NIM];
#pragma unroll
        for (int n1 = 0; n1 < 10; n1++) {
            float2 a = ipA[n1 * 32];
            float2 b = ipB[n1 * 32];
            float sn = g_sh[n1 * 32 + lane];
            xr[n1] = pk2(a.x * (shrA * sn), b.x * (shrB * sn));
            xi[n1] = pk2(a.y * (shrA * sn), b.y * (shrB * sn));
        }
    } else {
        const __half2* ipA = (const __half2*)inv + (size_t)colA * NIM + lane;
        const __half2* ipB = (const __half2*)inv + (size_t)colB * NIM + lane;
#pragma unroll
        for (int n1 = 0; n1 < 10; n1++) {
            float2 a = __half22float2(ipA[n1 * 32]);
            float2 b = __half22float2(ipB[n1 * 32]);
            xr[n1] = pk2(a.x, b.x);
            xi[n1] = pk2(a.y, b.y);
        }
    }

    // ---- per-lane butterfly twiddles (shared by both columns) ----
    float sc_s, sc_c;
    sincospif(-(float)(lane & 15) * (1.0f / 16.0f), &sc_s, &sc_c);
    const u2 T1c = dup2((lane & 16) ? sc_c : 1.0f);
    const u2 T1s = dup2((lane & 16) ? sc_s : 0.0f);
    sincospif(-(float)(lane & 7) * (1.0f / 8.0f), &sc_s, &sc_c);
    const u2 T2c = dup2((lane & 8) ? sc_c : 1.0f);
    const u2 T2s = dup2((lane & 8) ? sc_s : 0.0f);
    sincospif(-(float)(lane & 3) * (1.0f / 4.0f), &sc_s, &sc_c);
    const u2 T3c = dup2((lane & 4) ? sc_c : 1.0f);
    const u2 T3s = dup2((lane & 4) ? sc_s : 0.0f);
    const bool t4rot = (lane & 2) && (lane & 1);
    const u2 T4c = dup2(t4rot ? 0.0f : 1.0f);
    const u2 T4s = dup2(t4rot ? -1.0f : 0.0f);
    const u2 S16 = dup2((lane & 16) ? -1.0f : 1.0f);
    const u2 S8  = dup2((lane & 8)  ? -1.0f : 1.0f);
    const u2 S4  = dup2((lane & 4)  ? -1.0f : 1.0f);
    const u2 S2  = dup2((lane & 2)  ? -1.0f : 1.0f);
    const u2 S1  = dup2((lane & 1)  ? -1.0f : 1.0f);
    const u2 NEG1 = dup2(-1.0f);
    const int br = (int)(__brev((unsigned)lane) >> 27);          // bitrev5

    // ---- twiddle chains: W640^{n2 k} = wj * (W640^{5 n2})^t, k = j+5t ----
    sincospif(-(float)lane * (1.0f / 320.0f), &sc_s, &sc_c);     // W640^{n2}
    const u2 s1r = dup2(sc_c), s1i = dup2(sc_s), s1ni = dup2(-sc_s);
    sincospif(-(float)lane * (1.0f / 64.0f), &sc_s, &sc_c);      // W640^{5 n2}
    const u2 s5r = dup2(sc_c), s5i = dup2(sc_s), s5ni = dup2(-sc_s);
    u2 wjr = dup2(1.0f), wji = dup2(0.0f), wjni = dup2(0.0f);    // W640^{n2 j}

#define BFLY_RI(H, TC, TS, SD)                                          \
    do {                                                                \
        u2 o_re = __shfl_xor_sync(0xffffffffu, v_re, (H));              \
        u2 o_im = __shfl_xor_sync(0xffffffffu, v_im, (H));              \
        u2 t_re = fma2((SD), v_re, o_re);                               \
        u2 t_im = fma2((SD), v_im, o_im);                               \
        u2 t_imn = mul2(t_im, NEG1);                                    \
        v_re = fma2(t_imn, (TS), mul2(t_re, (TC)));                     \
        v_im = fma2(t_im,  (TC), mul2(t_re, (TS)));                     \
    } while (0)

    // ---- main loop: j = k % 5 ----
#pragma unroll
    for (int j = 0; j < 5; j++) {
        const int j2 = (2 * j) % 5;
        // A1: F0..F3 for this j (recomputed; only 8 u2 live)
        u2 f0r = xr[0], f0i = xi[0];
        u2 f1r = xr[1], f1i = xi[1];
        u2 f2r = xr[2], f2i = xi[2];
        u2 f3r = xr[3], f3i = xi[3];
        cfma_ri(f0r, f0i, xr[4], xi[4], W5R[j],  W5I[j]);
        cfma_ri(f0r, f0i, xr[8], xi[8], W5R[j2], W5I[j2]);
        cfma_ri(f1r, f1i, xr[5], xi[5], W5R[j],  W5I[j]);
        cfma_ri(f1r, f1i, xr[9], xi[9], W5R[j2], W5I[j2]);
        cfma_ri(f2r, f2i, xr[6], xi[6], W5R[j],  W5I[j]);
        cfma_ri(f3r, f3i, xr[7], xi[7], W5R[j],  W5I[j]);

        // inner twiddle chain starts at wj
        u2 tr = wjr, ti = wji, tni = wjni;

#pragma unroll
        for (int t = 0; t < 4; t++) {
            const int k  = j + 5 * t;
            const int ka = (2 * k) % 20, kb = (3 * k) % 20;
            u2 Xr = f0r, Xi = f0i;
            cfma_ri(Xr, Xi, f1r, f1i, W20R[k],  W20I[k]);
            cfma_ri(Xr, Xi, f2r, f2i, W20R[ka], W20I[ka]);
            cfma_ri(Xr, Xi, f3r, f3i, W20R[kb], W20I[kb]);

            // apply W640^{n2 k}
            u2 v_re = fma2(Xi, tni, mul2(Xr, tr));
            u2 v_im = fma2(Xi, tr,  mul2(Xr, ti));
            // advance inner chain by step5
            {
                u2 nr = fma2(ti, s5ni, mul2(tr, s5r));
                u2 ni = fma2(ti, s5r,  mul2(tr, s5i));
                tr = nr; ti = ni; tni = mul2(ni, NEG1);
            }

            // 32-pt cross-lane FFT
            BFLY_RI(16, T1c, T1s, S16);
            BFLY_RI(8,  T2c, T2s, S8);
            BFLY_RI(4,  T3c, T3s, S4);
            BFLY_RI(2,  T4c, T4s, S2);
            {
                u2 o_re = __shfl_xor_sync(0xffffffffu, v_re, 1);
                u2 o_im = __shfl_xor_sync(0xffffffffu, v_im, 1);
                v_re = fma2(S1, v_re, o_re);
                v_im = fma2(S1, v_im, o_im);
            }

            // phase C: lane holds X[k2 = br] for both cols
            float rA, rB, iA, iB;
            upk2(rA, rB, v_re);
            upk2(iA, iB, v_im);
            const int loc = (k * 32 + br) * SQ_PAD;
            buf[loc + 2 * w]     = pk2(rA, iA);
            buf[loc + 2 * w + 1] = pk2(rB, iB);
        }

        // advance outer chain by step1
        {
            u2 nr = fma2(wji, s1ni, mul2(wjr, s1r));
            u2 ni = fma2(wji, s1r,  mul2(wjr, s1i));
            wjr = nr; wji = ni; wjni = mul2(ni, NEG1);
        }
    }
#undef BFLY_RI
    __syncthreads();

    // ---- phase D: remapped coalesced fp16 global store ----
    // thread -> (k2b = tid>>3 in 0..15, c = tid&7); q = k1 + 20*k2.
    const int k2b = tid >> 3;
    const int c   = tid & 7;
    size_t out_base; int stride_q;
    if (MODE == 1) {
        // col = (p*16+cc)*320 + n  ->  out[((p*640+q)*16+cc)*320 + n]
        int pc = base_col / NIM, n0 = base_col % NIM;
        int p = pc >> 4, cc = pc & 15;
        out_base = (size_t)p * (640u * 16u * 320u) + (size_t)cc * 320u
                 + (size_t)n0 + c;
        stride_q = 16 * 320;
    } else {
        // col = (p*640+qq)*16 + coil  ->  out[((p*640+kk)*640+qq)*16 + coil]
        int pq = base_col >> 4, c0 = base_col & 15;
        int p = pq / KOS, qq = pq - p * KOS;
        out_base = (size_t)p * (640u * 640u * 16u) + (size_t)qq * 16u
                 + (size_t)c0 + c;
        stride_q = 640 * 16;
    }
#pragma unroll
    for (int k1 = 0; k1 < 20; k1++) {
#pragma unroll
        for (int h = 0; h < 2; h++) {
            const int k2 = k2b + 16 * h;
            u2 v = buf[(k1 * 32 + k2) * SQ_PAD + c];
            float vx, vy; upk2(vx, vy, v);
            out[out_base + (size_t)(k1 + 20 * k2) * stride_q] =
                __float22half2_rn(make_float2(vx, vy));
        }
    }
}

// ---------------------------------------------------------------------------
// KB interpolation: 6x6 taps, 16 coils per point; G fp16 coil-innermost so
// the 16 coil-lanes read 64B contiguous per tap. Weights/indices cached in
// registers.
// ---------------------------------------------------------------------------
__global__ __launch_bounds__(256) void interp_kernel(
    const float* __restrict__ traj, float2* __restrict__ out)
{
    __shared__ float s_wh[16][JTAPS], s_ww[16][JTAPS];
    __shared__ int   s_ih[16][JTAPS], s_iw[16][JTAPS];
    __shared__ float s_pr[16], s_pi[16];

    const int tid = threadIdx.x;
    const int cd  = tid & 15;                     // coil
    const int li  = tid >> 4;                     // point within block
    const int p   = blockIdx.y;
    const int l   = blockIdx.x * 16 + li;

    const float inv_i0a = g_inv_i0a;

    if (cd < 2) {
        float om = traj[(long)(p * 2 + cd) * KLEN + l];
        float t  = om * (320.0f / PI_F);
        float base = floorf(t - 3.0f);
#pragma unroll
        for (int j = 0; j < JTAPS; j++) {
            float kf  = base + (float)(j + 1);
            float u   = t - kf;
            float ua  = u * (1.0f / 3.0f);
            float arg = fmaxf(1.0f - ua * ua, 0.0f);
            float w   = i0f_dev(ALPHA_F * sqrtf(arg)) * inv_i0a;
            int ki  = (int)kf;
            int idx = ki % KOS; if (idx < 0) idx += KOS;
            if (cd == 0) { s_wh[li][j] = w; s_ih[li][j] = idx; }
            else         { s_ww[li][j] = w; s_iw[li][j] = idx; }
        }
        if (cd == 0) {
            float om1 = traj[(long)(p * 2 + 1) * KLEN + l];
            float th  = 160.0f * (om + om1);
            float sp, cp;
            sincosf(th, &sp, &cp);
            s_pr[li] = cp; s_pi[li] = sp;
        }
    }
    __syncthreads();

    float wh[JTAPS], ww[JTAPS];
    int   ihx[JTAPS], iwx[JTAPS];
#pragma unroll
    for (int j = 0; j < JTAPS; j++) {
        wh[j]  = s_wh[li][j];
        ww[j]  = s_ww[li][j];
        ihx[j] = s_ih[li][j];
        iwx[j] = s_iw[li][j] * 16;
    }
    const float pr = s_pr[li], pi = s_pi[li];

    const __half2* Gp = g_Gh + (size_t)p * (640u * 640u * 16u) + cd;
    float ar = 0.0f, ai = 0.0f;
#pragma unroll
    for (int j1 = 0; j1 < JTAPS; j1++) {
        const __half2* row = Gp + (size_t)ihx[j1] * (640u * 16u);
        const float w1 = wh[j1];
#pragma unroll
        for (int j2 = 0; j2 < JTAPS; j2++) {
            float2 v = __half22float2(row[iwx[j2]]);
            float  w = w1 * ww[j2];
            ar = fmaf(v.x, w, ar);
            ai = fmaf(v.y, w, ai);
        }
    }
    const float sc = 1.0f / 640.0f;               // ortho norm
    float2 o;
    o.x = (ar * pr - ai * pi) * sc;
    o.y = (ar * pi + ai * pr) * sc;
    out[(long)((p * NCOIL + cd) * KLEN) + l] = o;
}

// ---------------------------------------------------------------------------
// Launch
// ---------------------------------------------------------------------------
extern "C" void kernel_launch(void* const* d_in, const int* in_sizes, int n_in,
                              void* d_out, int out_size)
{
    const float2* image = (const float2*)d_in[0];   // (1,5,8,2,320,320,2)
    const float*  traj  = (const float*)d_in[1];    // (5,2,16000)

    __half2 *Rhp, *Ghp;
    cudaGetSymbolAddress((void**)&Rhp, g_Rh);
    cudaGetSymbolAddress((void**)&Ghp, g_Gh);

    const int smem_bytes = BUF_U2 * (int)sizeof(u2);   // 46080
    cudaFuncSetAttribute(fft640_kernel<1>,
                         cudaFuncAttributeMaxDynamicSharedMemorySize, smem_bytes);
    cudaFuncSetAttribute(fft640_kernel<2>,
                         cudaFuncAttributeMaxDynamicSharedMemorySize, smem_bytes);

    init_tables_kernel<<<2, 256>>>();

    // Stage 1: FFT along m (width), apodized.  cols = (p,c,n): 25600
    fft640_kernel<1><<<(PH * NCOIL * NIM) / 8, 128, smem_bytes>>>(
        (const void*)image, Rhp);

    // Stage 2: FFT along n (height).  cols = (p,q,c): 51200
    fft640_kernel<2><<<(PH * KOS * NCOIL) / 8, 128, smem_bytes>>>(
        (const void*)Rhp, Ghp);

    // Stage 3: KB interpolation + recentering phase + ortho scale
    {
        dim3 grid(KLEN / 16, PH);
        interp_kernel<<<grid, 256>>>(traj, (float2*)d_out);
    }
}